// round 1
// baseline (speedup 1.0000x reference)
#include <cuda_runtime.h>
#include <math.h>
#include <stdint.h>

#define NUM_HEADS 16
#define PADV (-4294967295.0f)   // rounds to -2^32 in fp32, matching jnp.float32(PAD)

// Scratch: head-split Q/K/V and context, each BT*D floats (4096*1024 = 4194304)
#define SCRATCH_ELEMS 4194304
__device__ float g_Qh[SCRATCH_ELEMS];
__device__ float g_Kh[SCRATCH_ELEMS];
__device__ float g_Vh[SCRATCH_ELEMS];
__device__ float g_Ctx[SCRATCH_ELEMS];

// ---------------------------------------------------------------------------
// GEMM: out[m,n] = sum_k A[m,k] * W[n,k] + bias[n], scattered into head-split
// layout dst[((head*B + b)*T + t)*depth + dd] with m=b*T+t, head=n/depth.
// 128x128 block tile, BK=8, 8x8 per-thread microtile, 256 threads.
// ---------------------------------------------------------------------------
__global__ __launch_bounds__(256) void gemm_bias_split_kernel(
    const float* __restrict__ A, const float* __restrict__ W,
    const float* __restrict__ bias, int sel,
    int M, int N, int K, int B, int T, int depth)
{
    float* dst = (sel == 0) ? g_Qh : (sel == 1) ? g_Kh : g_Vh;

    __shared__ float As[8][128];
    __shared__ float Bs[8][128];
    const int tid  = threadIdx.x;
    const int cRow = blockIdx.y * 128;
    const int cCol = blockIdx.x * 128;
    const int lRow = tid >> 1;
    const int lCol = (tid & 1) * 4;
    const int ty   = tid >> 4;
    const int tx   = tid & 15;

    float acc[8][8];
#pragma unroll
    for (int i = 0; i < 8; ++i)
#pragma unroll
        for (int j = 0; j < 8; ++j) acc[i][j] = 0.f;

    const float* Ap = A + (size_t)(cRow + lRow) * K + lCol;
    const float* Wp = W + (size_t)(cCol + lRow) * K + lCol;

    for (int k0 = 0; k0 < K; k0 += 8) {
        float4 av = *(const float4*)(Ap + k0);
        float4 wv = *(const float4*)(Wp + k0);
        As[lCol + 0][lRow] = av.x; As[lCol + 1][lRow] = av.y;
        As[lCol + 2][lRow] = av.z; As[lCol + 3][lRow] = av.w;
        Bs[lCol + 0][lRow] = wv.x; Bs[lCol + 1][lRow] = wv.y;
        Bs[lCol + 2][lRow] = wv.z; Bs[lCol + 3][lRow] = wv.w;
        __syncthreads();
#pragma unroll
        for (int k = 0; k < 8; ++k) {
            float4 a0 = *(const float4*)&As[k][ty * 8];
            float4 a1 = *(const float4*)&As[k][ty * 8 + 4];
            float4 b0 = *(const float4*)&Bs[k][tx * 8];
            float4 b1 = *(const float4*)&Bs[k][tx * 8 + 4];
            float ra[8] = {a0.x, a0.y, a0.z, a0.w, a1.x, a1.y, a1.z, a1.w};
            float rb[8] = {b0.x, b0.y, b0.z, b0.w, b1.x, b1.y, b1.z, b1.w};
#pragma unroll
            for (int i = 0; i < 8; ++i)
#pragma unroll
                for (int j = 0; j < 8; ++j)
                    acc[i][j] = fmaf(ra[i], rb[j], acc[i][j]);
        }
        __syncthreads();
    }

#pragma unroll
    for (int i = 0; i < 8; ++i) {
        int m = cRow + ty * 8 + i;
        int b = m / T, t = m % T;
#pragma unroll
        for (int j = 0; j < 8; ++j) {
            int n = cCol + tx * 8 + j;
            float v = acc[i][j] + bias[n];
            int head = n / depth, dd = n % depth;
            dst[(((size_t)head * B + b) * T + t) * depth + dd] = v;
        }
    }
}

// ---------------------------------------------------------------------------
// Fused attention: for head-batch n, query tile of 64 rows, flash-style online
// softmax over key tiles of 64. depth fixed at 64. 256 threads, each owns a
// 4x4 patch of the 64x64 S / O tiles. Key mask row = n / NUM_HEADS (this
// replicates the reference's batch-interleaved repeat against head-major
// scores -- intentional).
// ---------------------------------------------------------------------------
#define QS_STRIDE 68
#define KT_STRIDE 65
#define ATTN_SMEM_BYTES (3 * 64 * 68 * 4)

__global__ __launch_bounds__(256) void attn_kernel(
    const int* __restrict__ mask, const int* __restrict__ causality,
    int B, int T)
{
    extern __shared__ float sm[];
    float* Qs = sm;                 // [64][68] natural (row, dim)
    float* KP = sm + 64 * 68;       // K^T with stride 65; reused as P [64][68]
    float* Vs = sm + 2 * 64 * 68;   // [64][68] natural (key, dim)

    const int n   = blockIdx.y;
    const int q0  = blockIdx.x * 64;
    const int tid = threadIdx.x;
    const int ty  = tid >> 4;
    const int tx  = tid & 15;
    const int mrow = n / NUM_HEADS;
    const int caus = causality[0];

    const size_t baseQ = ((size_t)n * T + q0) * 64;
    for (int idx = tid; idx < 64 * 16; idx += 256) {
        int r = idx >> 4;
        int c = (idx & 15) * 4;
        *(float4*)&Qs[r * QS_STRIDE + c] =
            *(const float4*)&g_Qh[baseQ + (size_t)r * 64 + c];
    }

    float m_run[4], l_run[4], acc[4][4];
#pragma unroll
    for (int i = 0; i < 4; ++i) {
        m_run[i] = -INFINITY;
        l_run[i] = 0.f;
#pragma unroll
        for (int j = 0; j < 4; ++j) acc[i][j] = 0.f;
    }

    for (int k0 = 0; k0 < T; k0 += 64) {
        __syncthreads();   // previous-tile P/V reads complete (and Q stores on iter 0)
        const size_t baseK = ((size_t)n * T + k0) * 64;
        for (int idx = tid; idx < 64 * 16; idx += 256) {
            int r = idx >> 4;          // key row within tile
            int c = (idx & 15) * 4;    // dim
            float4 kv = *(const float4*)&g_Kh[baseK + (size_t)r * 64 + c];
            KP[(c + 0) * KT_STRIDE + r] = kv.x;
            KP[(c + 1) * KT_STRIDE + r] = kv.y;
            KP[(c + 2) * KT_STRIDE + r] = kv.z;
            KP[(c + 3) * KT_STRIDE + r] = kv.w;
            *(float4*)&Vs[r * QS_STRIDE + c] =
                *(const float4*)&g_Vh[baseK + (size_t)r * 64 + c];
        }
        __syncthreads();

        // S = Q K^T  (each thread 4 rows x 4 key-cols)
        float s[4][4];
#pragma unroll
        for (int i = 0; i < 4; ++i)
#pragma unroll
            for (int j = 0; j < 4; ++j) s[i][j] = 0.f;

#pragma unroll 4
        for (int d = 0; d < 64; ++d) {
            float ra[4], rb[4];
#pragma unroll
            for (int i = 0; i < 4; ++i) ra[i] = Qs[(ty * 4 + i) * QS_STRIDE + d];
#pragma unroll
            for (int j = 0; j < 4; ++j) rb[j] = KP[d * KT_STRIDE + tx * 4 + j];
#pragma unroll
            for (int i = 0; i < 4; ++i)
#pragma unroll
                for (int j = 0; j < 4; ++j)
                    s[i][j] = fmaf(ra[i], rb[j], s[i][j]);
        }

        // scale + key mask + optional causal mask
        float kmf[4];
#pragma unroll
        for (int j = 0; j < 4; ++j)
            kmf[j] = mask[(size_t)mrow * T + k0 + tx * 4 + j] ? PADV : 0.f;
#pragma unroll
        for (int i = 0; i < 4; ++i)
#pragma unroll
            for (int j = 0; j < 4; ++j) {
                float v = s[i][j] * 0.125f + kmf[j];
                if (caus && (k0 + tx * 4 + j) > (q0 + ty * 4 + i)) v = PADV;
                s[i][j] = v;
            }

        // online softmax (row stats replicated across the 16 tx lanes)
#pragma unroll
        for (int i = 0; i < 4; ++i) {
            float mx = fmaxf(fmaxf(s[i][0], s[i][1]), fmaxf(s[i][2], s[i][3]));
#pragma unroll
            for (int o = 8; o; o >>= 1)
                mx = fmaxf(mx, __shfl_xor_sync(0xffffffffu, mx, o));
            float m_new = fmaxf(m_run[i], mx);
            float corr  = __expf(m_run[i] - m_new);
            float psum  = 0.f;
#pragma unroll
            for (int j = 0; j < 4; ++j) {
                float p = __expf(s[i][j] - m_new);
                s[i][j] = p;
                psum += p;
            }
#pragma unroll
            for (int o = 8; o; o >>= 1)
                psum += __shfl_xor_sync(0xffffffffu, psum, o);
            l_run[i] = l_run[i] * corr + psum;
            m_run[i] = m_new;
#pragma unroll
            for (int j = 0; j < 4; ++j) acc[i][j] *= corr;
        }

        __syncthreads();   // all K^T reads done; safe to overwrite KP with P
#pragma unroll
        for (int i = 0; i < 4; ++i)
            *(float4*)&KP[(ty * 4 + i) * QS_STRIDE + tx * 4] =
                make_float4(s[i][0], s[i][1], s[i][2], s[i][3]);
        __syncthreads();

        // O += P @ V
#pragma unroll 4
        for (int ss = 0; ss < 64; ++ss) {
            float pr[4];
#pragma unroll
            for (int i = 0; i < 4; ++i) pr[i] = KP[(ty * 4 + i) * QS_STRIDE + ss];
            float4 v4 = *(const float4*)&Vs[ss * QS_STRIDE + tx * 4];
            float vb[4] = {v4.x, v4.y, v4.z, v4.w};
#pragma unroll
            for (int i = 0; i < 4; ++i)
#pragma unroll
                for (int j = 0; j < 4; ++j)
                    acc[i][j] = fmaf(pr[i], vb[j], acc[i][j]);
        }
    }

#pragma unroll
    for (int i = 0; i < 4; ++i) {
        float inv = 1.f / l_run[i];
        size_t base = ((size_t)n * T + q0 + ty * 4 + i) * 64 + tx * 4;
#pragma unroll
        for (int j = 0; j < 4; ++j)
            g_Ctx[base + j] = acc[i][j] * inv;
    }
}

// ---------------------------------------------------------------------------
// Merge heads + residual + LayerNorm. One block (256 threads) per (b,t) row.
// D assumed = 1024 (4 elements/thread).
// ---------------------------------------------------------------------------
__global__ __launch_bounds__(256) void merge_ln_kernel(
    const float* __restrict__ qin,
    const float* __restrict__ gamma, const float* __restrict__ beta,
    float* __restrict__ out, int B, int T, int D, int depth)
{
    const int row = blockIdx.x;
    const int b = row / T, t = row % T;
    const int tid = threadIdx.x;

    float vals[4];
    float sum = 0.f, sq = 0.f;
#pragma unroll
    for (int u = 0; u < 4; ++u) {
        int c = tid + u * 256;
        int head = c / depth, dd = c % depth;
        float v = g_Ctx[(((size_t)head * B + b) * T + t) * depth + dd] +
                  qin[(size_t)row * D + c];
        vals[u] = v;
        sum += v;
        sq  += v * v;
    }
#pragma unroll
    for (int o = 16; o; o >>= 1) {
        sum += __shfl_xor_sync(0xffffffffu, sum, o);
        sq  += __shfl_xor_sync(0xffffffffu, sq, o);
    }
    __shared__ float s1[8], s2[8];
    int w = tid >> 5, l = tid & 31;
    if (l == 0) { s1[w] = sum; s2[w] = sq; }
    __syncthreads();
    if (w == 0) {
        sum = (l < 8) ? s1[l] : 0.f;
        sq  = (l < 8) ? s2[l] : 0.f;
#pragma unroll
        for (int o = 4; o; o >>= 1) {
            sum += __shfl_xor_sync(0xffffffffu, sum, o);
            sq  += __shfl_xor_sync(0xffffffffu, sq, o);
        }
        if (l == 0) { s1[0] = sum; s2[0] = sq; }
    }
    __syncthreads();
    sum = s1[0];
    sq  = s2[0];
    float mu  = sum / (float)D;
    float var = sq / (float)D - mu * mu;
    float inv = rsqrtf(var + 1e-5f);
#pragma unroll
    for (int u = 0; u < 4; ++u) {
        int c = tid + u * 256;
        out[(size_t)row * D + c] = (vals[u] - mu) * inv * gamma[c] + beta[c];
    }
}

// ---------------------------------------------------------------------------
extern "C" void kernel_launch(void* const* d_in, const int* in_sizes, int n_in,
                              void* d_out, int out_size)
{
    const float* q    = (const float*)d_in[0];
    const float* k    = (const float*)d_in[1];
    const float* v    = (const float*)d_in[2];
    const int*   mask = (const int*)d_in[3];
    const int*   caus = (const int*)d_in[4];
    // d_in[5] = edge_fea (unused)
    const float* wq = (const float*)d_in[6];
    const float* bq = (const float*)d_in[7];
    const float* wk = (const float*)d_in[8];
    const float* bk = (const float*)d_in[9];
    const float* wv = (const float*)d_in[10];
    const float* bv = (const float*)d_in[11];
    const float* gamma = (const float*)d_in[12];
    const float* beta  = (const float*)d_in[13];
    float* out = (float*)d_out;

    const int D  = in_sizes[7];      // bq length
    const int BT = in_sizes[3];      // mask length = B*T
    int T = 2048;
    if (BT % T != 0) T = BT;
    const int B = BT / T;
    const int depth = D / NUM_HEADS;

    static int smem_set = -1;
    (void)smem_set;
    cudaFuncSetAttribute(attn_kernel, cudaFuncAttributeMaxDynamicSharedMemorySize,
                         ATTN_SMEM_BYTES);

    dim3 gemm_grid(D / 128, BT / 128);
    gemm_bias_split_kernel<<<gemm_grid, 256>>>(q, wq, bq, 0, BT, D, D, B, T, depth);
    gemm_bias_split_kernel<<<gemm_grid, 256>>>(k, wk, bk, 1, BT, D, D, B, T, depth);
    gemm_bias_split_kernel<<<gemm_grid, 256>>>(v, wv, bv, 2, BT, D, D, B, T, depth);

    dim3 attn_grid(T / 64, NUM_HEADS * B);
    attn_kernel<<<attn_grid, 256, ATTN_SMEM_BYTES>>>(mask, caus, B, T);

    merge_ln_kernel<<<BT, 256>>>(q, gamma, beta, out, B, T, D, depth);
}

// round 2
// speedup vs baseline: 3.3184x; 3.3184x over previous
#include <cuda_runtime.h>
#include <math.h>
#include <stdint.h>

#define NUM_HEADS 16
#define PADV (-4294967295.0f)   // rounds to -2^32 in fp32, matching jnp.float32(PAD)

// Scratch: head-split Q/K/V and context, each BT*D floats (4096*1024)
#define SCRATCH_ELEMS 4194304
__device__ float g_Qh[SCRATCH_ELEMS];
__device__ float g_Kh[SCRATCH_ELEMS];
__device__ float g_Vh[SCRATCH_ELEMS];
__device__ float g_Ctx[SCRATCH_ELEMS];

__device__ __forceinline__ uint32_t f2tf(float x) {
    uint32_t r;
    asm("cvt.rna.tf32.f32 %0, %1;" : "=r"(r) : "f"(x));
    return r;
}

__device__ __forceinline__ void mma_tf32(float* c,
                                         uint32_t a0, uint32_t a1, uint32_t a2, uint32_t a3,
                                         uint32_t b0, uint32_t b1) {
    asm volatile(
        "mma.sync.aligned.m16n8k8.row.col.f32.tf32.tf32.f32 "
        "{%0,%1,%2,%3}, {%4,%5,%6,%7}, {%8,%9}, {%0,%1,%2,%3};\n"
        : "+f"(c[0]), "+f"(c[1]), "+f"(c[2]), "+f"(c[3])
        : "r"(a0), "r"(a1), "r"(a2), "r"(a3), "r"(b0), "r"(b1));
}

// ---------------------------------------------------------------------------
// tf32 tensor-core GEMM: dst = head_split(A @ W^T + bias).
// Block tile 128x128, K-tile 32, 8 warps (4x2), warp tile 32x64.
// blockIdx.z selects q/k/v projection.
// ---------------------------------------------------------------------------
#define GST 36

__global__ __launch_bounds__(256) void gemm_tf32_kernel(
    const float* __restrict__ Aq, const float* __restrict__ Ak, const float* __restrict__ Av,
    const float* __restrict__ Wq, const float* __restrict__ Wk, const float* __restrict__ Wv,
    const float* __restrict__ bq, const float* __restrict__ bk, const float* __restrict__ bv,
    int K, int B, int T, int depth)
{
    const int sel = blockIdx.z;
    const float* A    = (sel == 0) ? Aq : (sel == 1) ? Ak : Av;
    const float* W    = (sel == 0) ? Wq : (sel == 1) ? Wk : Wv;
    const float* bias = (sel == 0) ? bq : (sel == 1) ? bk : bv;
    float* dst        = (sel == 0) ? g_Qh : (sel == 1) ? g_Kh : g_Vh;

    __shared__ uint32_t As[128 * GST];
    __shared__ uint32_t Bs[128 * GST];

    const int tid  = threadIdx.x;
    const int lane = tid & 31;
    const int warp = tid >> 5;
    const int wm   = (warp >> 1) * 32;
    const int wn   = (warp & 1) * 64;
    const int g    = lane >> 2;
    const int c    = lane & 3;
    const int cRow = blockIdx.y * 128;
    const int cCol = blockIdx.x * 128;

    float acc[2][8][4];
#pragma unroll
    for (int mb = 0; mb < 2; ++mb)
#pragma unroll
        for (int nb = 0; nb < 8; ++nb)
#pragma unroll
            for (int j = 0; j < 4; ++j) acc[mb][nb][j] = 0.f;

    for (int k0 = 0; k0 < K; k0 += 32) {
#pragma unroll
        for (int i = 0; i < 4; ++i) {
            int idx = tid + i * 256;
            int r = idx >> 3, c4 = (idx & 7) * 4;
            float4 av = *(const float4*)(A + (size_t)(cRow + r) * K + k0 + c4);
            As[r * GST + c4 + 0] = f2tf(av.x);
            As[r * GST + c4 + 1] = f2tf(av.y);
            As[r * GST + c4 + 2] = f2tf(av.z);
            As[r * GST + c4 + 3] = f2tf(av.w);
            float4 wv = *(const float4*)(W + (size_t)(cCol + r) * K + k0 + c4);
            Bs[r * GST + c4 + 0] = f2tf(wv.x);
            Bs[r * GST + c4 + 1] = f2tf(wv.y);
            Bs[r * GST + c4 + 2] = f2tf(wv.z);
            Bs[r * GST + c4 + 3] = f2tf(wv.w);
        }
        __syncthreads();
#pragma unroll
        for (int kk = 0; kk < 32; kk += 8) {
            uint32_t a[2][4];
#pragma unroll
            for (int mb = 0; mb < 2; ++mb) {
                int base = (wm + mb * 16 + g) * GST + kk + c;
                a[mb][0] = As[base];
                a[mb][1] = As[base + 8 * GST];
                a[mb][2] = As[base + 4];
                a[mb][3] = As[base + 8 * GST + 4];
            }
#pragma unroll
            for (int nb = 0; nb < 8; ++nb) {
                int bb = (wn + nb * 8 + g) * GST + kk + c;
                uint32_t b0 = Bs[bb], b1 = Bs[bb + 4];
                mma_tf32(acc[0][nb], a[0][0], a[0][1], a[0][2], a[0][3], b0, b1);
                mma_tf32(acc[1][nb], a[1][0], a[1][1], a[1][2], a[1][3], b0, b1);
            }
        }
        __syncthreads();
    }

#pragma unroll
    for (int mb = 0; mb < 2; ++mb) {
#pragma unroll
        for (int nb = 0; nb < 8; ++nb) {
            int col0 = cCol + wn + nb * 8 + 2 * c;
            float b0v = bias[col0], b1v = bias[col0 + 1];
            int head = col0 / depth, dd = col0 % depth;
#pragma unroll
            for (int rr = 0; rr < 2; ++rr) {
                int m = cRow + wm + mb * 16 + g + rr * 8;
                int bi = m / T, t = m % T;
                size_t o = (((size_t)head * B + bi) * T + t) * depth + dd;
                float2 v2 = make_float2(acc[mb][nb][rr * 2 + 0] + b0v,
                                        acc[mb][nb][rr * 2 + 1] + b1v);
                *(float2*)(dst + o) = v2;
            }
        }
    }
}

// ---------------------------------------------------------------------------
// Flash attention with tf32 tensor cores. 64-query tiles, 4 warps (128 thr),
// each warp owns a 16-row stripe. depth fixed at 64.
// smem: Qs[64][68] tf32 (Q pre-scaled by 1/8), KP[64][68] K tile then P tile,
//       Vs[64][72] natural [key][d], maskS[64].
// Key mask row = n / NUM_HEADS (reference's batch-interleaved repeat).
// ---------------------------------------------------------------------------
#define AST 68
#define VST 72
#define OFF_KP (64 * AST)
#define OFF_V  (2 * 64 * AST)
#define OFF_M  (2 * 64 * AST + 64 * VST)
#define ATTN_SMEM_BYTES ((OFF_M + 64) * 4)

__global__ __launch_bounds__(128) void attn_tf32_kernel(
    const int* __restrict__ mask, const int* __restrict__ causality,
    int B, int T)
{
    extern __shared__ uint32_t sm[];
    uint32_t* Qs = sm;
    uint32_t* KP = sm + OFF_KP;
    uint32_t* Vs = sm + OFF_V;
    int* maskS   = (int*)(sm + OFF_M);

    const int n    = blockIdx.y;
    const int q0   = blockIdx.x * 64;
    const int tid  = threadIdx.x;
    const int lane = tid & 31;
    const int warp = tid >> 5;
    const int g    = lane >> 2;
    const int c    = lane & 3;
    const int mrow = n / NUM_HEADS;
    const int caus = causality[0];
    const int rb   = warp * 16 + g;   // base row (within 64-tile) for this thread

    const size_t baseQ = ((size_t)n * T + q0) * 64;
#pragma unroll
    for (int i = 0; i < 8; ++i) {
        int idx = tid + i * 128;
        int r = idx >> 4, cc = (idx & 15) * 4;
        float4 qv = *(const float4*)&g_Qh[baseQ + (size_t)r * 64 + cc];
        Qs[r * AST + cc + 0] = f2tf(qv.x * 0.125f);
        Qs[r * AST + cc + 1] = f2tf(qv.y * 0.125f);
        Qs[r * AST + cc + 2] = f2tf(qv.z * 0.125f);
        Qs[r * AST + cc + 3] = f2tf(qv.w * 0.125f);
    }

    float m_run[2] = {-INFINITY, -INFINITY};
    float l_run[2] = {0.f, 0.f};
    float acc_o[8][4];
#pragma unroll
    for (int nb = 0; nb < 8; ++nb)
#pragma unroll
        for (int j = 0; j < 4; ++j) acc_o[nb][j] = 0.f;

    for (int k0 = 0; k0 < T; k0 += 64) {
        __syncthreads();   // prior-tile PV reads (and Q stores on iter 0) complete
        const size_t baseK = ((size_t)n * T + k0) * 64;
#pragma unroll
        for (int i = 0; i < 8; ++i) {
            int idx = tid + i * 128;
            int r = idx >> 4, cc = (idx & 15) * 4;
            float4 kv = *(const float4*)&g_Kh[baseK + (size_t)r * 64 + cc];
            KP[r * AST + cc + 0] = f2tf(kv.x);
            KP[r * AST + cc + 1] = f2tf(kv.y);
            KP[r * AST + cc + 2] = f2tf(kv.z);
            KP[r * AST + cc + 3] = f2tf(kv.w);
            float4 vv = *(const float4*)&g_Vh[baseK + (size_t)r * 64 + cc];
            Vs[r * VST + cc + 0] = f2tf(vv.x);
            Vs[r * VST + cc + 1] = f2tf(vv.y);
            Vs[r * VST + cc + 2] = f2tf(vv.z);
            Vs[r * VST + cc + 3] = f2tf(vv.w);
        }
        if (tid < 64) maskS[tid] = mask[(size_t)mrow * T + k0 + tid];
        __syncthreads();

        // ---- S = Q K^T on tensor cores ----
        float s[8][4];
#pragma unroll
        for (int nb = 0; nb < 8; ++nb)
#pragma unroll
            for (int j = 0; j < 4; ++j) s[nb][j] = 0.f;

#pragma unroll
        for (int kk = 0; kk < 64; kk += 8) {
            int ab = rb * AST + kk + c;
            uint32_t a0 = Qs[ab], a1 = Qs[ab + 8 * AST];
            uint32_t a2 = Qs[ab + 4], a3 = Qs[ab + 8 * AST + 4];
#pragma unroll
            for (int nb = 0; nb < 8; ++nb) {
                int bb = (nb * 8 + g) * AST + kk + c;
                mma_tf32(s[nb], a0, a1, a2, a3, KP[bb], KP[bb + 4]);
            }
        }

        // ---- mask + causal ----
#pragma unroll
        for (int nb = 0; nb < 8; ++nb) {
#pragma unroll
            for (int j = 0; j < 4; ++j) {
                int col = nb * 8 + 2 * c + (j & 1);
                float v = s[nb][j] + (maskS[col] ? PADV : 0.f);
                if (caus) {
                    int row = rb + ((j >> 1) << 3);
                    if ((k0 + col) > (q0 + row)) v = PADV;
                }
                s[nb][j] = v;
            }
        }

        // ---- online softmax (2 rows/thread; row stats across quad lanes) ----
#pragma unroll
        for (int r = 0; r < 2; ++r) {
            float mx = -INFINITY;
#pragma unroll
            for (int nb = 0; nb < 8; ++nb)
                mx = fmaxf(mx, fmaxf(s[nb][2 * r], s[nb][2 * r + 1]));
            mx = fmaxf(mx, __shfl_xor_sync(0xffffffffu, mx, 1));
            mx = fmaxf(mx, __shfl_xor_sync(0xffffffffu, mx, 2));
            float m_new = fmaxf(m_run[r], mx);
            float corr  = __expf(m_run[r] - m_new);
            float ps = 0.f;
#pragma unroll
            for (int nb = 0; nb < 8; ++nb) {
                float p0 = __expf(s[nb][2 * r] - m_new);
                float p1 = __expf(s[nb][2 * r + 1] - m_new);
                s[nb][2 * r] = p0; s[nb][2 * r + 1] = p1;
                ps += p0 + p1;
            }
            ps += __shfl_xor_sync(0xffffffffu, ps, 1);
            ps += __shfl_xor_sync(0xffffffffu, ps, 2);
            l_run[r] = l_run[r] * corr + ps;
            m_run[r] = m_new;
#pragma unroll
            for (int nb = 0; nb < 8; ++nb) {
                acc_o[nb][2 * r]     *= corr;
                acc_o[nb][2 * r + 1] *= corr;
            }
        }

        __syncthreads();   // all warps done reading K tile
        // ---- store P (tf32) into retired K buffer ----
#pragma unroll
        for (int nb = 0; nb < 8; ++nb) {
            int p0 = rb * AST + nb * 8 + 2 * c;
            KP[p0]     = f2tf(s[nb][0]);
            KP[p0 + 1] = f2tf(s[nb][1]);
            int p1 = (rb + 8) * AST + nb * 8 + 2 * c;
            KP[p1]     = f2tf(s[nb][2]);
            KP[p1 + 1] = f2tf(s[nb][3]);
        }
        __syncthreads();

        // ---- O += P V on tensor cores ----
#pragma unroll
        for (int kk = 0; kk < 64; kk += 8) {
            int ab = rb * AST + kk + c;
            uint32_t a0 = KP[ab], a1 = KP[ab + 8 * AST];
            uint32_t a2 = KP[ab + 4], a3 = KP[ab + 8 * AST + 4];
#pragma unroll
            for (int nb = 0; nb < 8; ++nb) {
                int bb = (kk + c) * VST + nb * 8 + g;
                mma_tf32(acc_o[nb], a0, a1, a2, a3, Vs[bb], Vs[bb + 4 * VST]);
            }
        }
    }

    // ---- write context ----
#pragma unroll
    for (int r = 0; r < 2; ++r) {
        float inv = 1.f / l_run[r];
        int row = q0 + rb + r * 8;
        size_t base = ((size_t)n * T + row) * 64;
#pragma unroll
        for (int nb = 0; nb < 8; ++nb) {
            float2 v2 = make_float2(acc_o[nb][2 * r] * inv, acc_o[nb][2 * r + 1] * inv);
            *(float2*)&g_Ctx[base + nb * 8 + 2 * c] = v2;
        }
    }
}

// ---------------------------------------------------------------------------
// Merge heads + residual + LayerNorm. One block (256 threads) per (b,t) row.
// ---------------------------------------------------------------------------
__global__ __launch_bounds__(256) void merge_ln_kernel(
    const float* __restrict__ qin,
    const float* __restrict__ gamma, const float* __restrict__ beta,
    float* __restrict__ out, int B, int T, int D, int depth)
{
    const int row = blockIdx.x;
    const int b = row / T, t = row % T;
    const int tid = threadIdx.x;

    float vals[4];
    float sum = 0.f, sq = 0.f;
#pragma unroll
    for (int u = 0; u < 4; ++u) {
        int cidx = tid + u * 256;
        int head = cidx / depth, dd = cidx % depth;
        float v = g_Ctx[(((size_t)head * B + b) * T + t) * depth + dd] +
                  qin[(size_t)row * D + cidx];
        vals[u] = v;
        sum += v;
        sq  += v * v;
    }
#pragma unroll
    for (int o = 16; o; o >>= 1) {
        sum += __shfl_xor_sync(0xffffffffu, sum, o);
        sq  += __shfl_xor_sync(0xffffffffu, sq, o);
    }
    __shared__ float s1[8], s2[8];
    int w = tid >> 5, l = tid & 31;
    if (l == 0) { s1[w] = sum; s2[w] = sq; }
    __syncthreads();
    if (w == 0) {
        sum = (l < 8) ? s1[l] : 0.f;
        sq  = (l < 8) ? s2[l] : 0.f;
#pragma unroll
        for (int o = 4; o; o >>= 1) {
            sum += __shfl_xor_sync(0xffffffffu, sum, o);
            sq  += __shfl_xor_sync(0xffffffffu, sq, o);
        }
        if (l == 0) { s1[0] = sum; s2[0] = sq; }
    }
    __syncthreads();
    sum = s1[0];
    sq  = s2[0];
    float mu  = sum / (float)D;
    float var = sq / (float)D - mu * mu;
    float inv = rsqrtf(var + 1e-5f);
#pragma unroll
    for (int u = 0; u < 4; ++u) {
        int cidx = tid + u * 256;
        out[(size_t)row * D + cidx] = (vals[u] - mu) * inv * gamma[cidx] + beta[cidx];
    }
}

// ---------------------------------------------------------------------------
extern "C" void kernel_launch(void* const* d_in, const int* in_sizes, int n_in,
                              void* d_out, int out_size)
{
    const float* q    = (const float*)d_in[0];
    const float* k    = (const float*)d_in[1];
    const float* v    = (const float*)d_in[2];
    const int*   mask = (const int*)d_in[3];
    const int*   caus = (const int*)d_in[4];
    // d_in[5] = edge_fea (unused)
    const float* wq = (const float*)d_in[6];
    const float* bq = (const float*)d_in[7];
    const float* wk = (const float*)d_in[8];
    const float* bk = (const float*)d_in[9];
    const float* wv = (const float*)d_in[10];
    const float* bv = (const float*)d_in[11];
    const float* gamma = (const float*)d_in[12];
    const float* beta  = (const float*)d_in[13];
    float* out = (float*)d_out;

    const int D  = in_sizes[7];      // bq length
    const int BT = in_sizes[3];      // mask length = B*T
    int T = 2048;
    if (BT % T != 0) T = BT;
    const int B = BT / T;
    const int depth = D / NUM_HEADS;

    cudaFuncSetAttribute(attn_tf32_kernel, cudaFuncAttributeMaxDynamicSharedMemorySize,
                         ATTN_SMEM_BYTES);

    dim3 gemm_grid(D / 128, BT / 128, 3);
    gemm_tf32_kernel<<<gemm_grid, 256>>>(q, k, v, wq, wk, wv, bq, bk, bv,
                                         D, B, T, depth);

    dim3 attn_grid(T / 64, NUM_HEADS * B);
    attn_tf32_kernel<<<attn_grid, 128, ATTN_SMEM_BYTES>>>(mask, caus, B, T);

    merge_ln_kernel<<<BT, 256>>>(q, gamma, beta, out, B, T, D, depth);
}

// round 3
// speedup vs baseline: 4.0536x; 1.2215x over previous
#include <cuda_runtime.h>
#include <math.h>
#include <stdint.h>

#define NUM_HEADS 16
#define PADV (-4294967295.0f)   // rounds to -2^32 in fp32, matching jnp.float32(PAD)

// Scratch: head-split Q/K/V and context, each BT*D floats (4096*1024)
#define SCRATCH_ELEMS 4194304
__device__ float g_Qh[SCRATCH_ELEMS];
__device__ float g_Kh[SCRATCH_ELEMS];
__device__ float g_Vh[SCRATCH_ELEMS];
__device__ float g_Ctx[SCRATCH_ELEMS];

// ---------------------------------------------------------------------------
// helpers
// ---------------------------------------------------------------------------
__device__ __forceinline__ uint32_t s2u(const void* p) {
    return (uint32_t)__cvta_generic_to_shared(p);
}
__device__ __forceinline__ void cpa16(uint32_t dst, const void* src) {
    asm volatile("cp.async.cg.shared.global [%0], [%1], 16;" :: "r"(dst), "l"(src));
}
__device__ __forceinline__ void cpa_commit() {
    asm volatile("cp.async.commit_group;" ::: "memory");
}

// tf32 mma; operands are raw fp32 bit patterns (HW truncates low mantissa bits)
__device__ __forceinline__ void mma_tf32(float* c,
                                         uint32_t a0, uint32_t a1, uint32_t a2, uint32_t a3,
                                         uint32_t b0, uint32_t b1) {
    asm volatile(
        "mma.sync.aligned.m16n8k8.row.col.f32.tf32.tf32.f32 "
        "{%0,%1,%2,%3}, {%4,%5,%6,%7}, {%8,%9}, {%0,%1,%2,%3};\n"
        : "+f"(c[0]), "+f"(c[1]), "+f"(c[2]), "+f"(c[3])
        : "r"(a0), "r"(a1), "r"(a2), "r"(a3), "r"(b0), "r"(b1));
}

// ---------------------------------------------------------------------------
// tf32 tensor-core GEMM with cp.async double buffering.
// dst = head_split(A @ W^T + bias). Block tile 128x128, K-tile 32,
// 8 warps (4x2), warp tile 32x64. blockIdx.z selects q/k/v projection.
// ---------------------------------------------------------------------------
#define GST 36
#define GSTAGE (128 * GST)
#define GEMM_SMEM_BYTES (4 * GSTAGE * 4)   // As[2] + Bs[2]

__global__ __launch_bounds__(256, 2) void gemm_tf32_kernel(
    const float* __restrict__ Aq, const float* __restrict__ Ak, const float* __restrict__ Av,
    const float* __restrict__ Wq, const float* __restrict__ Wk, const float* __restrict__ Wv,
    const float* __restrict__ bq, const float* __restrict__ bk, const float* __restrict__ bv,
    int K, int B, int T, int depth)
{
    const int sel = blockIdx.z;
    const float* A    = (sel == 0) ? Aq : (sel == 1) ? Ak : Av;
    const float* W    = (sel == 0) ? Wq : (sel == 1) ? Wk : Wv;
    const float* bias = (sel == 0) ? bq : (sel == 1) ? bk : bv;
    float* dst        = (sel == 0) ? g_Qh : (sel == 1) ? g_Kh : g_Vh;

    extern __shared__ uint32_t gsm[];
    uint32_t* As = gsm;                 // [2][128][GST]
    uint32_t* Bs = gsm + 2 * GSTAGE;    // [2][128][GST]
    const uint32_t abase = s2u(As);
    const uint32_t bbase = s2u(Bs);

    const int tid  = threadIdx.x;
    const int lane = tid & 31;
    const int warp = tid >> 5;
    const int wm   = (warp >> 1) * 32;
    const int wn   = (warp & 1) * 64;
    const int g    = lane >> 2;
    const int c    = lane & 3;
    const int cRow = blockIdx.y * 128;
    const int cCol = blockIdx.x * 128;

    float acc[2][8][4];
#pragma unroll
    for (int mb = 0; mb < 2; ++mb)
#pragma unroll
        for (int nb = 0; nb < 8; ++nb)
#pragma unroll
            for (int j = 0; j < 4; ++j) acc[mb][nb][j] = 0.f;

    auto issue = [&](int k0, int s) {
        uint32_t ab = abase + (uint32_t)(s * GSTAGE) * 4u;
        uint32_t bb = bbase + (uint32_t)(s * GSTAGE) * 4u;
#pragma unroll
        for (int i = 0; i < 4; ++i) {
            int idx = tid + i * 256;
            int r = idx >> 3, c4 = (idx & 7) * 4;
            cpa16(ab + (uint32_t)(r * GST + c4) * 4u,
                  A + (size_t)(cRow + r) * K + k0 + c4);
            cpa16(bb + (uint32_t)(r * GST + c4) * 4u,
                  W + (size_t)(cCol + r) * K + k0 + c4);
        }
    };

    const int NT = K / 32;
    issue(0, 0);
    cpa_commit();

    for (int it = 0; it < NT; ++it) {
        const int cur = it & 1;
        if (it > 0) __syncthreads();               // all warps done with buffer cur^1
        if (it + 1 < NT) {
            issue((it + 1) * 32, cur ^ 1);
            cpa_commit();
            asm volatile("cp.async.wait_group 1;" ::: "memory");
        } else {
            asm volatile("cp.async.wait_group 0;" ::: "memory");
        }
        __syncthreads();

        const uint32_t* Asc = As + cur * GSTAGE;
        const uint32_t* Bsc = Bs + cur * GSTAGE;
#pragma unroll
        for (int kk = 0; kk < 32; kk += 8) {
            uint32_t a[2][4];
#pragma unroll
            for (int mb = 0; mb < 2; ++mb) {
                int base = (wm + mb * 16 + g) * GST + kk + c;
                a[mb][0] = Asc[base];
                a[mb][1] = Asc[base + 8 * GST];
                a[mb][2] = Asc[base + 4];
                a[mb][3] = Asc[base + 8 * GST + 4];
            }
#pragma unroll
            for (int nb = 0; nb < 8; ++nb) {
                int bb = (wn + nb * 8 + g) * GST + kk + c;
                uint32_t b0 = Bsc[bb], b1 = Bsc[bb + 4];
                mma_tf32(acc[0][nb], a[0][0], a[0][1], a[0][2], a[0][3], b0, b1);
                mma_tf32(acc[1][nb], a[1][0], a[1][1], a[1][2], a[1][3], b0, b1);
            }
        }
    }

#pragma unroll
    for (int mb = 0; mb < 2; ++mb) {
#pragma unroll
        for (int nb = 0; nb < 8; ++nb) {
            int col0 = cCol + wn + nb * 8 + 2 * c;
            float b0v = bias[col0], b1v = bias[col0 + 1];
            int head = col0 / depth, dd = col0 % depth;
#pragma unroll
            for (int rr = 0; rr < 2; ++rr) {
                int m = cRow + wm + mb * 16 + g + rr * 8;
                int bi = m / T, t = m % T;
                size_t o = (((size_t)head * B + bi) * T + t) * depth + dd;
                float2 v2 = make_float2(acc[mb][nb][rr * 2 + 0] + b0v,
                                        acc[mb][nb][rr * 2 + 1] + b1v);
                *(float2*)(dst + o) = v2;
            }
        }
    }
}

// ---------------------------------------------------------------------------
// Flash attention, tf32 tensor cores, cp.async double-buffered K/V/mask.
// 64-query tiles, 4 warps (128 thr), each warp owns a 16-row stripe.
// Scale 1/8 folded into the mask fmaf. P buffer is warp-private (rows).
// Key mask row = n / NUM_HEADS (reference's batch-interleaved repeat).
// ---------------------------------------------------------------------------
#define AST 68
#define VST 72
#define QW  (64 * AST)             // 4352 words
#define KW  (64 * AST)
#define VW  (64 * VST)             // 4608 words
#define OFF_K  QW
#define OFF_V  (QW + 2 * KW)       // 13056
#define OFF_P  (OFF_V + 2 * VW)    // 22272
#define OFF_MK (OFF_P + QW)        // 26624
#define ATTN_SMEM_BYTES ((OFF_MK + 128) * 4)   // 107008 B

__global__ __launch_bounds__(128) void attn_tf32_kernel(
    const int* __restrict__ mask, const int* __restrict__ causality,
    int B, int T)
{
    extern __shared__ uint32_t sm[];
    uint32_t* Qs = sm;
    uint32_t* Ks = sm + OFF_K;
    uint32_t* Vs = sm + OFF_V;
    uint32_t* Ps = sm + OFF_P;
    int* maskS   = (int*)(sm + OFF_MK);

    const int n    = blockIdx.y;
    const int q0   = blockIdx.x * 64;
    const int tid  = threadIdx.x;
    const int lane = tid & 31;
    const int warp = tid >> 5;
    const int g    = lane >> 2;
    const int c    = lane & 3;
    const int mrow = n / NUM_HEADS;
    const int caus = causality[0];
    const int rb   = warp * 16 + g;   // base row within 64-tile

    // Q: raw fp32 via cp.async (scale folded into mask step)
    const size_t baseQ = ((size_t)n * T + q0) * 64;
    {
        uint32_t qb = s2u(Qs);
#pragma unroll
        for (int i = 0; i < 8; ++i) {
            int idx = tid + i * 128;
            int r = idx >> 4, cc = (idx & 15) * 4;
            cpa16(qb + (uint32_t)(r * AST + cc) * 4u,
                  g_Qh + baseQ + (size_t)r * 64 + cc);
        }
    }

    auto issue_kv = [&](int t, int s) {
        const size_t baseK = ((size_t)n * T + t * 64) * 64;
        uint32_t kb = s2u(Ks) + (uint32_t)(s * KW) * 4u;
        uint32_t vb = s2u(Vs) + (uint32_t)(s * VW) * 4u;
#pragma unroll
        for (int i = 0; i < 8; ++i) {
            int idx = tid + i * 128;
            int r = idx >> 4, cc = (idx & 15) * 4;
            cpa16(kb + (uint32_t)(r * AST + cc) * 4u,
                  g_Kh + baseK + (size_t)r * 64 + cc);
            cpa16(vb + (uint32_t)(r * VST + cc) * 4u,
                  g_Vh + baseK + (size_t)r * 64 + cc);
        }
        if (tid < 16)
            cpa16(s2u(maskS) + (uint32_t)(s * 64 + tid * 4) * 4u,
                  mask + (size_t)mrow * T + t * 64 + tid * 4);
    };

    const int NT = T / 64;
    issue_kv(0, 0);
    cpa_commit();

    float m_run[2] = {-INFINITY, -INFINITY};
    float l_run[2] = {0.f, 0.f};
    float acc_o[8][4];
#pragma unroll
    for (int nb = 0; nb < 8; ++nb)
#pragma unroll
        for (int j = 0; j < 4; ++j) acc_o[nb][j] = 0.f;

    for (int t = 0; t < NT; ++t) {
        const int cur = t & 1;
        if (t > 0) __syncthreads();             // all warps done with buffer cur^1
        if (t + 1 < NT) {
            issue_kv(t + 1, cur ^ 1);
            cpa_commit();
            asm volatile("cp.async.wait_group 1;" ::: "memory");
        } else {
            asm volatile("cp.async.wait_group 0;" ::: "memory");
        }
        __syncthreads();

        const uint32_t* Kc = Ks + cur * KW;
        const uint32_t* Vc = Vs + cur * VW;
        const int* mk = maskS + cur * 64;

        // ---- S = Q K^T ----
        float s[8][4];
#pragma unroll
        for (int nb = 0; nb < 8; ++nb)
#pragma unroll
            for (int j = 0; j < 4; ++j) s[nb][j] = 0.f;

#pragma unroll
        for (int kk = 0; kk < 64; kk += 8) {
            int ab = rb * AST + kk + c;
            uint32_t a0 = Qs[ab], a1 = Qs[ab + 8 * AST];
            uint32_t a2 = Qs[ab + 4], a3 = Qs[ab + 8 * AST + 4];
#pragma unroll
            for (int nb = 0; nb < 8; ++nb) {
                int bb = (nb * 8 + g) * AST + kk + c;
                mma_tf32(s[nb], a0, a1, a2, a3, Kc[bb], Kc[bb + 4]);
            }
        }

        // ---- scale (1/8) + key mask + optional causal ----
#pragma unroll
        for (int nb = 0; nb < 8; ++nb) {
#pragma unroll
            for (int j = 0; j < 4; ++j) {
                int col = nb * 8 + 2 * c + (j & 1);
                float v = fmaf(s[nb][j], 0.125f, mk[col] ? PADV : 0.f);
                if (caus) {
                    int row = rb + ((j >> 1) << 3);
                    if ((t * 64 + col) > (q0 + row)) v = PADV;
                }
                s[nb][j] = v;
            }
        }

        // ---- online softmax (2 rows/thread; stats across quad lanes) ----
#pragma unroll
        for (int r = 0; r < 2; ++r) {
            float mx = -INFINITY;
#pragma unroll
            for (int nb = 0; nb < 8; ++nb)
                mx = fmaxf(mx, fmaxf(s[nb][2 * r], s[nb][2 * r + 1]));
            mx = fmaxf(mx, __shfl_xor_sync(0xffffffffu, mx, 1));
            mx = fmaxf(mx, __shfl_xor_sync(0xffffffffu, mx, 2));
            float m_new = fmaxf(m_run[r], mx);
            float corr  = __expf(m_run[r] - m_new);
            float ps = 0.f;
#pragma unroll
            for (int nb = 0; nb < 8; ++nb) {
                float p0 = __expf(s[nb][2 * r] - m_new);
                float p1 = __expf(s[nb][2 * r + 1] - m_new);
                s[nb][2 * r] = p0; s[nb][2 * r + 1] = p1;
                ps += p0 + p1;
            }
            ps += __shfl_xor_sync(0xffffffffu, ps, 1);
            ps += __shfl_xor_sync(0xffffffffu, ps, 2);
            l_run[r] = l_run[r] * corr + ps;
            m_run[r] = m_new;
#pragma unroll
            for (int nb = 0; nb < 8; ++nb) {
                acc_o[nb][2 * r]     *= corr;
                acc_o[nb][2 * r + 1] *= corr;
            }
        }

        // ---- P to warp-private smem rows (raw fp32 bits) ----
        __syncwarp();   // prior PV reads of Ps by this warp's lanes complete
#pragma unroll
        for (int nb = 0; nb < 8; ++nb) {
            int p0 = rb * AST + nb * 8 + 2 * c;
            Ps[p0]     = __float_as_uint(s[nb][0]);
            Ps[p0 + 1] = __float_as_uint(s[nb][1]);
            int p1 = (rb + 8) * AST + nb * 8 + 2 * c;
            Ps[p1]     = __float_as_uint(s[nb][2]);
            Ps[p1 + 1] = __float_as_uint(s[nb][3]);
        }
        __syncwarp();

        // ---- O += P V ----
#pragma unroll
        for (int kk = 0; kk < 64; kk += 8) {
            int ab = rb * AST + kk + c;
            uint32_t a0 = Ps[ab], a1 = Ps[ab + 8 * AST];
            uint32_t a2 = Ps[ab + 4], a3 = Ps[ab + 8 * AST + 4];
#pragma unroll
            for (int nb = 0; nb < 8; ++nb) {
                int bb = (kk + c) * VST + nb * 8 + g;
                mma_tf32(acc_o[nb], a0, a1, a2, a3, Vc[bb], Vc[bb + 4 * VST]);
            }
        }
    }

    // ---- write context ----
#pragma unroll
    for (int r = 0; r < 2; ++r) {
        float inv = 1.f / l_run[r];
        int row = q0 + rb + r * 8;
        size_t base = ((size_t)n * T + row) * 64;
#pragma unroll
        for (int nb = 0; nb < 8; ++nb) {
            float2 v2 = make_float2(acc_o[nb][2 * r] * inv, acc_o[nb][2 * r + 1] * inv);
            *(float2*)&g_Ctx[base + nb * 8 + 2 * c] = v2;
        }
    }
}

// ---------------------------------------------------------------------------
// Merge heads + residual + LayerNorm. One block (256 threads) per (b,t) row.
// ---------------------------------------------------------------------------
__global__ __launch_bounds__(256) void merge_ln_kernel(
    const float* __restrict__ qin,
    const float* __restrict__ gamma, const float* __restrict__ beta,
    float* __restrict__ out, int B, int T, int D, int depth)
{
    const int row = blockIdx.x;
    const int b = row / T, t = row % T;
    const int tid = threadIdx.x;

    float vals[4];
    float sum = 0.f, sq = 0.f;
#pragma unroll
    for (int u = 0; u < 4; ++u) {
        int cidx = tid + u * 256;
        int head = cidx / depth, dd = cidx % depth;
        float v = g_Ctx[(((size_t)head * B + b) * T + t) * depth + dd] +
                  qin[(size_t)row * D + cidx];
        vals[u] = v;
        sum += v;
        sq  += v * v;
    }
#pragma unroll
    for (int o = 16; o; o >>= 1) {
        sum += __shfl_xor_sync(0xffffffffu, sum, o);
        sq  += __shfl_xor_sync(0xffffffffu, sq, o);
    }
    __shared__ float s1[8], s2[8];
    int w = tid >> 5, l = tid & 31;
    if (l == 0) { s1[w] = sum; s2[w] = sq; }
    __syncthreads();
    if (w == 0) {
        sum = (l < 8) ? s1[l] : 0.f;
        sq  = (l < 8) ? s2[l] : 0.f;
#pragma unroll
        for (int o = 4; o; o >>= 1) {
            sum += __shfl_xor_sync(0xffffffffu, sum, o);
            sq  += __shfl_xor_sync(0xffffffffu, sq, o);
        }
        if (l == 0) { s1[0] = sum; s2[0] = sq; }
    }
    __syncthreads();
    sum = s1[0];
    sq  = s2[0];
    float mu  = sum / (float)D;
    float var = sq / (float)D - mu * mu;
    float inv = rsqrtf(var + 1e-5f);
#pragma unroll
    for (int u = 0; u < 4; ++u) {
        int cidx = tid + u * 256;
        out[(size_t)row * D + cidx] = (vals[u] - mu) * inv * gamma[cidx] + beta[cidx];
    }
}

// ---------------------------------------------------------------------------
extern "C" void kernel_launch(void* const* d_in, const int* in_sizes, int n_in,
                              void* d_out, int out_size)
{
    const float* q    = (const float*)d_in[0];
    const float* k    = (const float*)d_in[1];
    const float* v    = (const float*)d_in[2];
    const int*   mask = (const int*)d_in[3];
    const int*   caus = (const int*)d_in[4];
    // d_in[5] = edge_fea (unused)
    const float* wq = (const float*)d_in[6];
    const float* bq = (const float*)d_in[7];
    const float* wk = (const float*)d_in[8];
    const float* bk = (const float*)d_in[9];
    const float* wv = (const float*)d_in[10];
    const float* bv = (const float*)d_in[11];
    const float* gamma = (const float*)d_in[12];
    const float* beta  = (const float*)d_in[13];
    float* out = (float*)d_out;

    const int D  = in_sizes[7];      // bq length
    const int BT = in_sizes[3];      // mask length = B*T
    int T = 2048;
    if (BT % T != 0) T = BT;
    const int B = BT / T;
    const int depth = D / NUM_HEADS;

    cudaFuncSetAttribute(gemm_tf32_kernel, cudaFuncAttributeMaxDynamicSharedMemorySize,
                         GEMM_SMEM_BYTES);
    cudaFuncSetAttribute(attn_tf32_kernel, cudaFuncAttributeMaxDynamicSharedMemorySize,
                         ATTN_SMEM_BYTES);

    dim3 gemm_grid(D / 128, BT / 128, 3);
    gemm_tf32_kernel<<<gemm_grid, 256, GEMM_SMEM_BYTES>>>(q, k, v, wq, wk, wv,
                                                          bq, bk, bv, D, B, T, depth);

    dim3 attn_grid(T / 64, NUM_HEADS * B);
    attn_tf32_kernel<<<attn_grid, 128, ATTN_SMEM_BYTES>>>(mask, caus, B, T);

    merge_ln_kernel<<<BT, 256>>>(q, gamma, beta, out, B, T, D, depth);
}

// round 5
// speedup vs baseline: 6.3296x; 1.5615x over previous
#include <cuda_runtime.h>
#include <cuda_fp16.h>
#include <math.h>
#include <stdint.h>

#define NUM_HEADS 16
#define PADV (-4294967295.0f)   // rounds to -2^32 in fp32, matching jnp.float32(PAD)

// fp16 scratch
#define A_ELEMS 4194304          // BT*D = 4096*1024
#define W_ELEMS 1048576          // D*D
__device__ __half g_Aq[A_ELEMS];
__device__ __half g_Ak[A_ELEMS];
__device__ __half g_Av[A_ELEMS];
__device__ __half g_Wq[W_ELEMS];
__device__ __half g_Wk[W_ELEMS];
__device__ __half g_Wv[W_ELEMS];
__device__ __half g_Qh[A_ELEMS];   // [n][t][d] head-split
__device__ __half g_Kh[A_ELEMS];   // [n][t][d]
__device__ __half g_VhT[A_ELEMS];  // [n*depth + d][T]  (transposed)
__device__ float  g_Ctx[A_ELEMS];

// ---------------------------------------------------------------------------
// helpers
// ---------------------------------------------------------------------------
__device__ __forceinline__ uint32_t s2u(const void* p) {
    return (uint32_t)__cvta_generic_to_shared(p);
}
__device__ __forceinline__ void cpa16(uint32_t dst, const void* src) {
    asm volatile("cp.async.cg.shared.global [%0], [%1], 16;" :: "r"(dst), "l"(src));
}
__device__ __forceinline__ void cpa_commit() {
    asm volatile("cp.async.commit_group;" ::: "memory");
}
__device__ __forceinline__ void mma_f16(float* c,
                                        uint32_t a0, uint32_t a1, uint32_t a2, uint32_t a3,
                                        uint32_t b0, uint32_t b1) {
    asm volatile(
        "mma.sync.aligned.m16n8k16.row.col.f32.f16.f16.f32 "
        "{%0,%1,%2,%3}, {%4,%5,%6,%7}, {%8,%9}, {%0,%1,%2,%3};\n"
        : "+f"(c[0]), "+f"(c[1]), "+f"(c[2]), "+f"(c[3])
        : "r"(a0), "r"(a1), "r"(a2), "r"(a3), "r"(b0), "r"(b1));
}
__device__ __forceinline__ uint32_t pack_h2(float lo, float hi) {
    half2 h = __floats2half2_rn(lo, hi);
    return *(uint32_t*)&h;
}

// ---------------------------------------------------------------------------
// fp32 -> fp16 conversion (8 elements/thread). sel picks destination.
// ---------------------------------------------------------------------------
__global__ __launch_bounds__(256) void cvt_kernel(const float* __restrict__ src,
                                                  int sel, int n)
{
    __half* dst = (sel == 0) ? g_Aq : (sel == 1) ? g_Ak : (sel == 2) ? g_Av
                : (sel == 3) ? g_Wq : (sel == 4) ? g_Wk : g_Wv;
    int i = (blockIdx.x * 256 + threadIdx.x) * 8;
    if (i >= n) return;
    float4 v0 = *(const float4*)(src + i);
    float4 v1 = *(const float4*)(src + i + 4);
    uint4 o;
    o.x = pack_h2(v0.x, v0.y);
    o.y = pack_h2(v0.z, v0.w);
    o.z = pack_h2(v1.x, v1.y);
    o.w = pack_h2(v1.z, v1.w);
    *(uint4*)(dst + i) = o;
}

// ---------------------------------------------------------------------------
// fp16 tensor-core GEMM: head_split(A @ W^T + bias).
// Block tile 128x128, BK=64 (fp16), cp.async double buffered, 8 warps (4x2),
// warp tile 32x64, mma m16n8k16. sel: 0=Q, 1=K, 2=V(transposed output).
// smem rows padded to 72 halves (36 u32) for conflict-free fragment LDS.
// ---------------------------------------------------------------------------
#define GST32 36
#define GBUF (128 * GST32)                    // u32 per buffer
#define GEMM_SMEM_BYTES (4 * GBUF * 4)        // As[2]+Bs[2] = 73728 B

__global__ __launch_bounds__(256, 2) void gemm_f16_kernel(
    const float* __restrict__ bq, const float* __restrict__ bk, const float* __restrict__ bv,
    int K, int B, int T, int depth)
{
    const int sel = blockIdx.z;
    const __half* A = (sel == 0) ? g_Aq : (sel == 1) ? g_Ak : g_Av;
    const __half* W = (sel == 0) ? g_Wq : (sel == 1) ? g_Wk : g_Wv;
    const float* bias = (sel == 0) ? bq : (sel == 1) ? bk : bv;

    extern __shared__ uint32_t gsm[];
    uint32_t* As = gsm;
    uint32_t* Bs = gsm + 2 * GBUF;
    const uint32_t abase = s2u(As);
    const uint32_t bbase = s2u(Bs);

    const int tid  = threadIdx.x;
    const int lane = tid & 31;
    const int warp = tid >> 5;
    const int wm   = (warp >> 1) * 32;
    const int wn   = (warp & 1) * 64;
    const int g    = lane >> 2;
    const int c    = lane & 3;
    const int cRow = blockIdx.y * 128;
    const int cCol = blockIdx.x * 128;

    float acc[2][8][4];
#pragma unroll
    for (int mb = 0; mb < 2; ++mb)
#pragma unroll
        for (int nb = 0; nb < 8; ++nb)
#pragma unroll
            for (int j = 0; j < 4; ++j) acc[mb][nb][j] = 0.f;

    auto issue = [&](int k0, int s) {
        uint32_t ab = abase + (uint32_t)(s * GBUF) * 4u;
        uint32_t bb = bbase + (uint32_t)(s * GBUF) * 4u;
#pragma unroll
        for (int i = 0; i < 4; ++i) {          // 128 rows x 8 chunks of 16B
            int idx = tid + i * 256;
            int r = idx >> 3, ch = idx & 7;
            cpa16(ab + (uint32_t)(r * 144 + ch * 16),
                  A + (size_t)(cRow + r) * K + k0 + ch * 8);
            cpa16(bb + (uint32_t)(r * 144 + ch * 16),
                  W + (size_t)(cCol + r) * K + k0 + ch * 8);
        }
    };

    const int NT = K / 64;
    issue(0, 0);
    cpa_commit();

    for (int it = 0; it < NT; ++it) {
        const int cur = it & 1;
        if (it > 0) __syncthreads();
        if (it + 1 < NT) {
            issue((it + 1) * 64, cur ^ 1);
            cpa_commit();
            asm volatile("cp.async.wait_group 1;" ::: "memory");
        } else {
            asm volatile("cp.async.wait_group 0;" ::: "memory");
        }
        __syncthreads();

        const uint32_t* Asc = As + cur * GBUF;
        const uint32_t* Bsc = Bs + cur * GBUF;
#pragma unroll
        for (int kk = 0; kk < 4; ++kk) {       // 4 x k16
            uint32_t a[2][4];
#pragma unroll
            for (int mb = 0; mb < 2; ++mb) {
                int base = (wm + mb * 16 + g) * GST32 + kk * 8 + c;
                a[mb][0] = Asc[base];
                a[mb][1] = Asc[base + 8 * GST32];
                a[mb][2] = Asc[base + 4];
                a[mb][3] = Asc[base + 8 * GST32 + 4];
            }
#pragma unroll
            for (int nb = 0; nb < 8; ++nb) {
                int bb = (wn + nb * 8 + g) * GST32 + kk * 8 + c;
                uint32_t b0 = Bsc[bb], b1 = Bsc[bb + 4];
                mma_f16(acc[0][nb], a[0][0], a[0][1], a[0][2], a[0][3], b0, b1);
                mma_f16(acc[1][nb], a[1][0], a[1][1], a[1][2], a[1][3], b0, b1);
            }
        }
    }

    // epilogue: bias add + head-split, fp16 outputs.
#pragma unroll
    for (int mb = 0; mb < 2; ++mb) {
#pragma unroll
        for (int nb = 0; nb < 8; ++nb) {
            int col0 = cCol + wn + nb * 8 + 2 * c;
            float b0v = bias[col0], b1v = bias[col0 + 1];
            int head = col0 / depth, dd = col0 % depth;
#pragma unroll
            for (int rr = 0; rr < 2; ++rr) {
                int m = cRow + wm + mb * 16 + g + rr * 8;
                int bi = m / T, t = m % T;
                float v0 = acc[mb][nb][rr * 2 + 0] + b0v;
                float v1 = acc[mb][nb][rr * 2 + 1] + b1v;
                if (sel < 2) {
                    __half* dst = (sel == 0) ? g_Qh : g_Kh;
                    uint32_t p = pack_h2(v0, v1);
                    *(uint32_t*)(dst + (((size_t)head * B + bi) * T + t) * depth + dd) = p;
                } else {
                    size_t rbase = ((size_t)head * B + bi) * depth;
                    g_VhT[(rbase + dd)     * T + t] = __float2half_rn(v0);
                    g_VhT[(rbase + dd + 1) * T + t] = __float2half_rn(v1);
                }
            }
        }
    }
}

// ---------------------------------------------------------------------------
// Flash attention, fp16 m16n8k16, cp.async double-buffered K/V^T/mask.
// 64-query tiles, 4 warps, warp owns 16-row stripe. Scale 1/8 folded into
// the mask fmaf. Key mask row = n / NUM_HEADS (reference's interleave).
// smem (u32 units, rows of 36 u32 = 72 halves):
//   Qs[2304] | Ks[2][2304] | VT[2][2304] | Ps[2304] | mask[2][64]
// ---------------------------------------------------------------------------
#define TST 36
#define TILE32 (64 * TST)        // 2304
#define OFF_K  TILE32
#define OFF_V  (3 * TILE32)
#define OFF_P  (5 * TILE32)
#define OFF_MK (6 * TILE32)
#define ATTN_SMEM_BYTES ((OFF_MK + 128) * 4)   // 55808 B

__global__ __launch_bounds__(128) void attn_f16_kernel(
    const int* __restrict__ mask, const int* __restrict__ causality,
    int B, int T)
{
    extern __shared__ uint32_t sm[];
    uint32_t* Qs = sm;
    uint32_t* Ks = sm + OFF_K;
    uint32_t* VT = sm + OFF_V;
    uint32_t* Ps = sm + OFF_P;
    int* maskS   = (int*)(sm + OFF_MK);

    const int n    = blockIdx.y;
    const int q0   = blockIdx.x * 64;
    const int tid  = threadIdx.x;
    const int lane = tid & 31;
    const int warp = tid >> 5;
    const int g    = lane >> 2;
    const int c    = lane & 3;
    const int mrow = n / NUM_HEADS;
    const int caus = causality[0];
    const int rbq  = warp * 16 + g;

    // Q tile: 64 rows x 64 halves (128B = 8 chunks)
    {
        const __half* src = g_Qh + ((size_t)n * T + q0) * 64;
        uint32_t qb = s2u(Qs);
#pragma unroll
        for (int i = 0; i < 4; ++i) {
            int idx = tid + i * 128;
            int r = idx >> 3, ch = idx & 7;
            cpa16(qb + (uint32_t)(r * 144 + ch * 16), src + (size_t)r * 64 + ch * 8);
        }
    }

    auto issue_kv = [&](int t, int s) {
        const __half* ksrc = g_Kh + ((size_t)n * T + t * 64) * 64;
        const __half* vsrc = g_VhT + (size_t)n * 64 * T + t * 64;  // row d, col t
        uint32_t kb = s2u(Ks) + (uint32_t)(s * TILE32) * 4u;
        uint32_t vb = s2u(VT) + (uint32_t)(s * TILE32) * 4u;
#pragma unroll
        for (int i = 0; i < 4; ++i) {
            int idx = tid + i * 128;
            int r = idx >> 3, ch = idx & 7;
            cpa16(kb + (uint32_t)(r * 144 + ch * 16), ksrc + (size_t)r * 64 + ch * 8);
            cpa16(vb + (uint32_t)(r * 144 + ch * 16), vsrc + (size_t)r * T + ch * 8);
        }
        if (tid < 16)
            cpa16(s2u(maskS) + (uint32_t)(s * 64 + tid * 4) * 4u,
                  mask + (size_t)mrow * T + t * 64 + tid * 4);
    };

    const int NT = T / 64;
    issue_kv(0, 0);
    cpa_commit();

    float m_run[2] = {-INFINITY, -INFINITY};
    float l_run[2] = {0.f, 0.f};
    float acc_o[8][4];
#pragma unroll
    for (int nb = 0; nb < 8; ++nb)
#pragma unroll
        for (int j = 0; j < 4; ++j) acc_o[nb][j] = 0.f;

    for (int t = 0; t < NT; ++t) {
        const int cur = t & 1;
        if (t > 0) __syncthreads();
        if (t + 1 < NT) {
            issue_kv(t + 1, cur ^ 1);
            cpa_commit();
            asm volatile("cp.async.wait_group 1;" ::: "memory");
        } else {
            asm volatile("cp.async.wait_group 0;" ::: "memory");
        }
        __syncthreads();

        const uint32_t* Kc = Ks + cur * TILE32;
        const uint32_t* Vc = VT + cur * TILE32;
        const int* mk = maskS + cur * 64;

        // ---- S = Q K^T ----
        float s[8][4];
#pragma unroll
        for (int nb = 0; nb < 8; ++nb)
#pragma unroll
            for (int j = 0; j < 4; ++j) s[nb][j] = 0.f;

#pragma unroll
        for (int kk = 0; kk < 4; ++kk) {
            int ab = rbq * TST + kk * 8 + c;
            uint32_t a0 = Qs[ab], a1 = Qs[ab + 8 * TST];
            uint32_t a2 = Qs[ab + 4], a3 = Qs[ab + 8 * TST + 4];
#pragma unroll
            for (int nb = 0; nb < 8; ++nb) {
                int bb = (nb * 8 + g) * TST + kk * 8 + c;
                mma_f16(s[nb], a0, a1, a2, a3, Kc[bb], Kc[bb + 4]);
            }
        }

        // ---- scale (1/8) + key mask + optional causal ----
#pragma unroll
        for (int nb = 0; nb < 8; ++nb) {
#pragma unroll
            for (int j = 0; j < 4; ++j) {
                int col = nb * 8 + 2 * c + (j & 1);
                float v = fmaf(s[nb][j], 0.125f, mk[col] ? PADV : 0.f);
                if (caus) {
                    int row = rbq + ((j >> 1) << 3);
                    if ((t * 64 + col) > (q0 + row)) v = PADV;
                }
                s[nb][j] = v;
            }
        }

        // ---- online softmax (2 rows/thread; stats across quad lanes) ----
#pragma unroll
        for (int r = 0; r < 2; ++r) {
            float mx = -INFINITY;
#pragma unroll
            for (int nb = 0; nb < 8; ++nb)
                mx = fmaxf(mx, fmaxf(s[nb][2 * r], s[nb][2 * r + 1]));
            mx = fmaxf(mx, __shfl_xor_sync(0xffffffffu, mx, 1));
            mx = fmaxf(mx, __shfl_xor_sync(0xffffffffu, mx, 2));
            float m_new = fmaxf(m_run[r], mx);
            float corr  = __expf(m_run[r] - m_new);
            float ps = 0.f;
#pragma unroll
            for (int nb = 0; nb < 8; ++nb) {
                float p0 = __expf(s[nb][2 * r] - m_new);
                float p1 = __expf(s[nb][2 * r + 1] - m_new);
                s[nb][2 * r] = p0; s[nb][2 * r + 1] = p1;
                ps += p0 + p1;
            }
            ps += __shfl_xor_sync(0xffffffffu, ps, 1);
            ps += __shfl_xor_sync(0xffffffffu, ps, 2);
            l_run[r] = l_run[r] * corr + ps;
            m_run[r] = m_new;
#pragma unroll
            for (int nb = 0; nb < 8; ++nb) {
                acc_o[nb][2 * r]     *= corr;
                acc_o[nb][2 * r + 1] *= corr;
            }
        }

        // ---- P (fp16) to warp-private smem rows ----
        __syncwarp();
#pragma unroll
        for (int nb = 0; nb < 8; ++nb) {
            Ps[rbq * TST + nb * 4 + c]       = pack_h2(s[nb][0], s[nb][1]);
            Ps[(rbq + 8) * TST + nb * 4 + c] = pack_h2(s[nb][2], s[nb][3]);
        }
        __syncwarp();

        // ---- O += P V  (B operand from V^T: rows = d, k = s) ----
#pragma unroll
        for (int kk = 0; kk < 4; ++kk) {
            int ab = rbq * TST + kk * 8 + c;
            uint32_t a0 = Ps[ab], a1 = Ps[ab + 8 * TST];
            uint32_t a2 = Ps[ab + 4], a3 = Ps[ab + 8 * TST + 4];
#pragma unroll
            for (int nb = 0; nb < 8; ++nb) {
                int bb = (nb * 8 + g) * TST + kk * 8 + c;
                mma_f16(acc_o[nb], a0, a1, a2, a3, Vc[bb], Vc[bb + 4]);
            }
        }
    }

    // ---- write context (fp32) ----
#pragma unroll
    for (int r = 0; r < 2; ++r) {
        float inv = 1.f / l_run[r];
        int row = q0 + rbq + r * 8;
        size_t base = ((size_t)n * T + row) * 64;
#pragma unroll
        for (int nb = 0; nb < 8; ++nb) {
            float2 v2 = make_float2(acc_o[nb][2 * r] * inv, acc_o[nb][2 * r + 1] * inv);
            *(float2*)&g_Ctx[base + nb * 8 + 2 * c] = v2;
        }
    }
}

// ---------------------------------------------------------------------------
// Merge heads + residual + LayerNorm. One block (256 threads) per (b,t) row.
// ---------------------------------------------------------------------------
__global__ __launch_bounds__(256) void merge_ln_kernel(
    const float* __restrict__ qin,
    const float* __restrict__ gamma, const float* __restrict__ beta,
    float* __restrict__ out, int B, int T, int D, int depth)
{
    const int row = blockIdx.x;
    const int b = row / T, t = row % T;
    const int tid = threadIdx.x;

    float vals[4];
    float sum = 0.f, sq = 0.f;
#pragma unroll
    for (int u = 0; u < 4; ++u) {
        int cidx = tid + u * 256;
        int head = cidx / depth, dd = cidx % depth;
        float v = g_Ctx[(((size_t)head * B + b) * T + t) * depth + dd] +
                  qin[(size_t)row * D + cidx];
        vals[u] = v;
        sum += v;
        sq  += v * v;
    }
#pragma unroll
    for (int o = 16; o; o >>= 1) {
        sum += __shfl_xor_sync(0xffffffffu, sum, o);
        sq  += __shfl_xor_sync(0xffffffffu, sq, o);
    }
    __shared__ float s1[8], s2[8];
    int w = tid >> 5, l = tid & 31;
    if (l == 0) { s1[w] = sum; s2[w] = sq; }
    __syncthreads();
    if (w == 0) {
        sum = (l < 8) ? s1[l] : 0.f;
        sq  = (l < 8) ? s2[l] : 0.f;
#pragma unroll
        for (int o = 4; o; o >>= 1) {
            sum += __shfl_xor_sync(0xffffffffu, sum, o);
            sq  += __shfl_xor_sync(0xffffffffu, sq, o);
        }
        if (l == 0) { s1[0] = sum; s2[0] = sq; }
    }
    __syncthreads();
    sum = s1[0];
    sq  = s2[0];
    float mu  = sum / (float)D;
    float var = sq / (float)D - mu * mu;
    float inv = rsqrtf(var + 1e-5f);
#pragma unroll
    for (int u = 0; u < 4; ++u) {
        int cidx = tid + u * 256;
        out[(size_t)row * D + cidx] = (vals[u] - mu) * inv * gamma[cidx] + beta[cidx];
    }
}

// ---------------------------------------------------------------------------
extern "C" void kernel_launch(void* const* d_in, const int* in_sizes, int n_in,
                              void* d_out, int out_size)
{
    const float* q    = (const float*)d_in[0];
    const float* k    = (const float*)d_in[1];
    const float* v    = (const float*)d_in[2];
    const int*   mask = (const int*)d_in[3];
    const int*   caus = (const int*)d_in[4];
    // d_in[5] = edge_fea (unused)
    const float* wq = (const float*)d_in[6];
    const float* bq = (const float*)d_in[7];
    const float* wk = (const float*)d_in[8];
    const float* bk = (const float*)d_in[9];
    const float* wv = (const float*)d_in[10];
    const float* bv = (const float*)d_in[11];
    const float* gamma = (const float*)d_in[12];
    const float* beta  = (const float*)d_in[13];
    float* out = (float*)d_out;

    const int D  = in_sizes[7];      // bq length
    const int BT = in_sizes[3];      // mask length = B*T
    int T = 2048;
    if (BT % T != 0) T = BT;
    const int B = BT / T;
    const int depth = D / NUM_HEADS;
    const int nA = BT * D;
    const int nW = D * D;

    cudaFuncSetAttribute(gemm_f16_kernel, cudaFuncAttributeMaxDynamicSharedMemorySize,
                         GEMM_SMEM_BYTES);
    cudaFuncSetAttribute(attn_f16_kernel, cudaFuncAttributeMaxDynamicSharedMemorySize,
                         ATTN_SMEM_BYTES);

    cvt_kernel<<<nA / (8 * 256), 256>>>(q,  0, nA);
    cvt_kernel<<<nA / (8 * 256), 256>>>(k,  1, nA);
    cvt_kernel<<<nA / (8 * 256), 256>>>(v,  2, nA);
    cvt_kernel<<<(nW + 2047) / 2048, 256>>>(wq, 3, nW);
    cvt_kernel<<<(nW + 2047) / 2048, 256>>>(wk, 4, nW);
    cvt_kernel<<<(nW + 2047) / 2048, 256>>>(wv, 5, nW);

    dim3 gemm_grid(D / 128, BT / 128, 3);
    gemm_f16_kernel<<<gemm_grid, 256, GEMM_SMEM_BYTES>>>(bq, bk, bv, D, B, T, depth);

    dim3 attn_grid(T / 64, NUM_HEADS * B);
    attn_f16_kernel<<<attn_grid, 128, ATTN_SMEM_BYTES>>>(mask, caus, B, T);

    merge_ln_kernel<<<BT, 256>>>(q, gamma, beta, out, B, T, D, depth);
}

// round 6
// speedup vs baseline: 6.6013x; 1.0429x over previous
#include <cuda_runtime.h>
#include <cuda_fp16.h>
#include <math.h>
#include <stdint.h>

#define NUM_HEADS 16
#define PADV (-4294967295.0f)    // rounds to -2^32 in fp32, matching jnp.float32(PAD)
#define LOG2E 1.4426950408889634f
#define SCALE2 (0.125f * LOG2E)
#define PADL2 (-6.196328e9f)     // PADV * LOG2E

// fp16 scratch
#define A_ELEMS 4194304          // BT*D = 4096*1024
#define W_ELEMS 1048576          // D*D
__device__ __half g_Aq[A_ELEMS];
__device__ __half g_Ak[A_ELEMS];
__device__ __half g_Av[A_ELEMS];
__device__ __half g_Wq[W_ELEMS];
__device__ __half g_Wk[W_ELEMS];
__device__ __half g_Wv[W_ELEMS];
__device__ __half g_Qh[A_ELEMS];   // [n][t][d] head-split
__device__ __half g_Kh[A_ELEMS];   // [n][t][d]
__device__ __half g_VhT[A_ELEMS];  // [n*64 + d][T]  (transposed)
__device__ float  g_Ctx[A_ELEMS];

// ---------------------------------------------------------------------------
// helpers
// ---------------------------------------------------------------------------
__device__ __forceinline__ uint32_t s2u(const void* p) {
    return (uint32_t)__cvta_generic_to_shared(p);
}
__device__ __forceinline__ void cpa16(uint32_t dst, const void* src) {
    asm volatile("cp.async.cg.shared.global [%0], [%1], 16;" :: "r"(dst), "l"(src));
}
__device__ __forceinline__ void cpa_commit() {
    asm volatile("cp.async.commit_group;" ::: "memory");
}
__device__ __forceinline__ void mma_f16(float* c,
                                        uint32_t a0, uint32_t a1, uint32_t a2, uint32_t a3,
                                        uint32_t b0, uint32_t b1) {
    asm volatile(
        "mma.sync.aligned.m16n8k16.row.col.f32.f16.f16.f32 "
        "{%0,%1,%2,%3}, {%4,%5,%6,%7}, {%8,%9}, {%0,%1,%2,%3};\n"
        : "+f"(c[0]), "+f"(c[1]), "+f"(c[2]), "+f"(c[3])
        : "r"(a0), "r"(a1), "r"(a2), "r"(a3), "r"(b0), "r"(b1));
}
__device__ __forceinline__ uint32_t pack_h2(float lo, float hi) {
    half2 h = __floats2half2_rn(lo, hi);
    return *(uint32_t*)&h;
}

// ---------------------------------------------------------------------------
// One fused fp32 -> fp16 conversion kernel for q,k,v,wq,wk,wv.
// ---------------------------------------------------------------------------
__global__ __launch_bounds__(256) void cvt_all_kernel(
    const float* __restrict__ q, const float* __restrict__ k, const float* __restrict__ v,
    const float* __restrict__ wq, const float* __restrict__ wk, const float* __restrict__ wv,
    int nA, int nW)
{
    long i = ((long)blockIdx.x * 256 + threadIdx.x) * 8;
    const long total = 3L * nA + 3L * nW;
    if (i >= total) return;

    const float* src;
    __half* dst;
    long off;
    if (i < (long)nA)            { src = q;  dst = g_Aq; off = i; }
    else if (i < 2L * nA)        { src = k;  dst = g_Ak; off = i - nA; }
    else if (i < 3L * nA)        { src = v;  dst = g_Av; off = i - 2L * nA; }
    else if (i < 3L * nA + nW)   { src = wq; dst = g_Wq; off = i - 3L * nA; }
    else if (i < 3L * nA + 2L * nW) { src = wk; dst = g_Wk; off = i - 3L * nA - nW; }
    else                         { src = wv; dst = g_Wv; off = i - 3L * nA - 2L * nW; }

    float4 v0 = *(const float4*)(src + off);
    float4 v1 = *(const float4*)(src + off + 4);
    uint4 o;
    o.x = pack_h2(v0.x, v0.y);
    o.y = pack_h2(v0.z, v0.w);
    o.z = pack_h2(v1.x, v1.y);
    o.w = pack_h2(v1.z, v1.w);
    *(uint4*)(dst + off) = o;
}

// ---------------------------------------------------------------------------
// fp16 tensor-core GEMM: head_split(A @ W^T + bias).
// Block tile 128x128, BK=64, cp.async double buffered, 8 warps (4x2),
// warp tile 32x64, mma m16n8k16. sel: 0=Q, 1=K, 2=V (transposed via smem).
// ---------------------------------------------------------------------------
#define GST32 36
#define GBUF (128 * GST32)                    // u32 per buffer
#define GEMM_SMEM_BYTES (4 * GBUF * 4)        // 73728 B (also fits transpose buf)
#define TRST 136                              // halves, transpose buffer stride

__global__ __launch_bounds__(256, 2) void gemm_f16_kernel(
    const float* __restrict__ bq, const float* __restrict__ bk, const float* __restrict__ bv,
    int K, int B, int T, int depth)
{
    const int sel = blockIdx.z;
    const __half* A = (sel == 0) ? g_Aq : (sel == 1) ? g_Ak : g_Av;
    const __half* W = (sel == 0) ? g_Wq : (sel == 1) ? g_Wk : g_Wv;
    const float* bias = (sel == 0) ? bq : (sel == 1) ? bk : bv;

    extern __shared__ uint32_t gsm[];
    uint32_t* As = gsm;
    uint32_t* Bs = gsm + 2 * GBUF;
    const uint32_t abase = s2u(As);
    const uint32_t bbase = s2u(Bs);

    const int tid  = threadIdx.x;
    const int lane = tid & 31;
    const int warp = tid >> 5;
    const int wm   = (warp >> 1) * 32;
    const int wn   = (warp & 1) * 64;
    const int g    = lane >> 2;
    const int c    = lane & 3;
    const int cRow = blockIdx.y * 128;
    const int cCol = blockIdx.x * 128;

    float acc[2][8][4];
#pragma unroll
    for (int mb = 0; mb < 2; ++mb)
#pragma unroll
        for (int nb = 0; nb < 8; ++nb)
#pragma unroll
            for (int j = 0; j < 4; ++j) acc[mb][nb][j] = 0.f;

    auto issue = [&](int k0, int s) {
        uint32_t ab = abase + (uint32_t)(s * GBUF) * 4u;
        uint32_t bb = bbase + (uint32_t)(s * GBUF) * 4u;
#pragma unroll
        for (int i = 0; i < 4; ++i) {
            int idx = tid + i * 256;
            int r = idx >> 3, ch = idx & 7;
            cpa16(ab + (uint32_t)(r * 144 + ch * 16),
                  A + (size_t)(cRow + r) * K + k0 + ch * 8);
            cpa16(bb + (uint32_t)(r * 144 + ch * 16),
                  W + (size_t)(cCol + r) * K + k0 + ch * 8);
        }
    };

    const int NT = K / 64;
    issue(0, 0);
    cpa_commit();

    for (int it = 0; it < NT; ++it) {
        const int cur = it & 1;
        if (it > 0) __syncthreads();
        if (it + 1 < NT) {
            issue((it + 1) * 64, cur ^ 1);
            cpa_commit();
            asm volatile("cp.async.wait_group 1;" ::: "memory");
        } else {
            asm volatile("cp.async.wait_group 0;" ::: "memory");
        }
        __syncthreads();

        const uint32_t* Asc = As + cur * GBUF;
        const uint32_t* Bsc = Bs + cur * GBUF;
#pragma unroll
        for (int kk = 0; kk < 4; ++kk) {
            uint32_t a[2][4];
#pragma unroll
            for (int mb = 0; mb < 2; ++mb) {
                int base = (wm + mb * 16 + g) * GST32 + kk * 8 + c;
                a[mb][0] = Asc[base];
                a[mb][1] = Asc[base + 8 * GST32];
                a[mb][2] = Asc[base + 4];
                a[mb][3] = Asc[base + 8 * GST32 + 4];
            }
#pragma unroll
            for (int nb = 0; nb < 8; ++nb) {
                int bb = (wn + nb * 8 + g) * GST32 + kk * 8 + c;
                uint32_t b0 = Bsc[bb], b1 = Bsc[bb + 4];
                mma_f16(acc[0][nb], a[0][0], a[0][1], a[0][2], a[0][3], b0, b1);
                mma_f16(acc[1][nb], a[1][0], a[1][1], a[1][2], a[1][3], b0, b1);
            }
        }
    }

    if (sel < 2) {
        // Q/K epilogue: bias + head-split, coalesced u32 stores.
        __half* dst = (sel == 0) ? g_Qh : g_Kh;
#pragma unroll
        for (int mb = 0; mb < 2; ++mb) {
#pragma unroll
            for (int nb = 0; nb < 8; ++nb) {
                int col0 = cCol + wn + nb * 8 + 2 * c;
                float b0v = bias[col0], b1v = bias[col0 + 1];
                int head = col0 / depth, dd = col0 % depth;
#pragma unroll
                for (int rr = 0; rr < 2; ++rr) {
                    int m = cRow + wm + mb * 16 + g + rr * 8;
                    int bi = m / T, t = m % T;
                    uint32_t p = pack_h2(acc[mb][nb][rr * 2 + 0] + b0v,
                                         acc[mb][nb][rr * 2 + 1] + b1v);
                    *(uint32_t*)(dst + (((size_t)head * B + bi) * T + t) * depth + dd) = p;
                }
            }
        }
    } else {
        // V epilogue: transpose through smem, coalesced V^T rows.
        __syncthreads();
        __half* tb = (__half*)gsm;     // [128 cols][TRST] (col-major of the tile)
#pragma unroll
        for (int mb = 0; mb < 2; ++mb) {
#pragma unroll
            for (int nb = 0; nb < 8; ++nb) {
                int col0 = wn + nb * 8 + 2 * c;
                float b0v = bias[cCol + col0], b1v = bias[cCol + col0 + 1];
#pragma unroll
                for (int rr = 0; rr < 2; ++rr) {
                    int m = wm + mb * 16 + g + rr * 8;
                    tb[col0 * TRST + m]       = __float2half_rn(acc[mb][nb][rr * 2 + 0] + b0v);
                    tb[(col0 + 1) * TRST + m] = __float2half_rn(acc[mb][nb][rr * 2 + 1] + b1v);
                }
            }
        }
        __syncthreads();
        const int bi = cRow / T;
        const int t0 = cRow % T;
#pragma unroll
        for (int i = 0; i < 8; ++i) {
            int idx = tid + i * 256;
            int dl = idx >> 4, c16 = idx & 15;      // 128 d-rows x 16 chunks of 16B
            int dg = cCol + dl;
            size_t vrow = ((size_t)(dg >> 6) * B + bi) * 64 + (dg & 63);
            *(uint4*)(g_VhT + vrow * T + t0 + c16 * 8) =
                *(const uint4*)(tb + dl * TRST + c16 * 8);
        }
    }
}

// ---------------------------------------------------------------------------
// Flash attention, fp16 m16n8k16. 128-query tiles, 8 warps (256 thr),
// cp.async double-buffered K/V^T/mask, exp2-domain softmax.
// Key mask row = n / NUM_HEADS (reference's batch-interleaved repeat).
// ---------------------------------------------------------------------------
#define TST 36
#define QTILE32 (128 * TST)      // 4608
#define KTILE32 (64 * TST)       // 2304
#define OFF_K  QTILE32
#define OFF_V  (QTILE32 + 2 * KTILE32)
#define OFF_P  (QTILE32 + 4 * KTILE32)
#define OFF_MK (2 * QTILE32 + 4 * KTILE32)
#define ATTN_SMEM_BYTES ((OFF_MK + 128) * 4)    // 74240 B

__global__ __launch_bounds__(256) void attn_f16_kernel(
    const int* __restrict__ mask, const int* __restrict__ causality,
    int B, int T)
{
    extern __shared__ uint32_t sm[];
    uint32_t* Qs = sm;
    uint32_t* Ks = sm + OFF_K;
    uint32_t* VT = sm + OFF_V;
    uint32_t* Ps = sm + OFF_P;
    int* maskS   = (int*)(sm + OFF_MK);

    const int n    = blockIdx.y;
    const int q0   = blockIdx.x * 128;
    const int tid  = threadIdx.x;
    const int lane = tid & 31;
    const int warp = tid >> 5;
    const int g    = lane >> 2;
    const int c    = lane & 3;
    const int mrow = n / NUM_HEADS;
    const int caus = causality[0];
    const int rbq  = warp * 16 + g;

    // Q tile: 128 rows x 64 halves
    {
        const __half* src = g_Qh + ((size_t)n * T + q0) * 64;
        uint32_t qb = s2u(Qs);
#pragma unroll
        for (int i = 0; i < 4; ++i) {
            int idx = tid + i * 256;
            int r = idx >> 3, ch = idx & 7;
            cpa16(qb + (uint32_t)(r * 144 + ch * 16), src + (size_t)r * 64 + ch * 8);
        }
    }

    auto issue_kv = [&](int t, int s) {
        const __half* ksrc = g_Kh + ((size_t)n * T + t * 64) * 64;
        const __half* vsrc = g_VhT + (size_t)n * 64 * T + t * 64;
        uint32_t kb = s2u(Ks) + (uint32_t)(s * KTILE32) * 4u;
        uint32_t vb = s2u(VT) + (uint32_t)(s * KTILE32) * 4u;
#pragma unroll
        for (int i = 0; i < 2; ++i) {
            int idx = tid + i * 256;
            int r = idx >> 3, ch = idx & 7;
            cpa16(kb + (uint32_t)(r * 144 + ch * 16), ksrc + (size_t)r * 64 + ch * 8);
            cpa16(vb + (uint32_t)(r * 144 + ch * 16), vsrc + (size_t)r * T + ch * 8);
        }
        if (tid < 16)
            cpa16(s2u(maskS) + (uint32_t)(s * 64 + tid * 4) * 4u,
                  mask + (size_t)mrow * T + t * 64 + tid * 4);
    };

    const int NT = T / 64;
    issue_kv(0, 0);
    cpa_commit();

    float m_run[2] = {-INFINITY, -INFINITY};
    float l_run[2] = {0.f, 0.f};
    float acc_o[8][4];
#pragma unroll
    for (int nb = 0; nb < 8; ++nb)
#pragma unroll
        for (int j = 0; j < 4; ++j) acc_o[nb][j] = 0.f;

    for (int t = 0; t < NT; ++t) {
        const int cur = t & 1;
        if (t > 0) __syncthreads();
        if (t + 1 < NT) {
            issue_kv(t + 1, cur ^ 1);
            cpa_commit();
            asm volatile("cp.async.wait_group 1;" ::: "memory");
        } else {
            asm volatile("cp.async.wait_group 0;" ::: "memory");
        }
        __syncthreads();

        const uint32_t* Kc = Ks + cur * KTILE32;
        const uint32_t* Vc = VT + cur * KTILE32;
        const int* mk = maskS + cur * 64;

        // ---- S = Q K^T ----
        float s[8][4];
#pragma unroll
        for (int nb = 0; nb < 8; ++nb)
#pragma unroll
            for (int j = 0; j < 4; ++j) s[nb][j] = 0.f;

#pragma unroll
        for (int kk = 0; kk < 4; ++kk) {
            int ab = rbq * TST + kk * 8 + c;
            uint32_t a0 = Qs[ab], a1 = Qs[ab + 8 * TST];
            uint32_t a2 = Qs[ab + 4], a3 = Qs[ab + 8 * TST + 4];
#pragma unroll
            for (int nb = 0; nb < 8; ++nb) {
                int bb = (nb * 8 + g) * TST + kk * 8 + c;
                mma_f16(s[nb], a0, a1, a2, a3, Kc[bb], Kc[bb + 4]);
            }
        }

        // ---- scale (exp2 domain) + key mask + optional causal ----
#pragma unroll
        for (int nb = 0; nb < 8; ++nb) {
#pragma unroll
            for (int j = 0; j < 4; ++j) {
                int col = nb * 8 + 2 * c + (j & 1);
                float v = fmaf(s[nb][j], SCALE2, mk[col] ? PADL2 : 0.f);
                if (caus) {
                    int row = rbq + ((j >> 1) << 3);
                    if ((t * 64 + col) > (q0 + row)) v = PADL2;
                }
                s[nb][j] = v;
            }
        }

        // ---- online softmax (2 rows/thread; stats across quad lanes) ----
#pragma unroll
        for (int r = 0; r < 2; ++r) {
            float mx = -INFINITY;
#pragma unroll
            for (int nb = 0; nb < 8; ++nb)
                mx = fmaxf(mx, fmaxf(s[nb][2 * r], s[nb][2 * r + 1]));
            mx = fmaxf(mx, __shfl_xor_sync(0xffffffffu, mx, 1));
            mx = fmaxf(mx, __shfl_xor_sync(0xffffffffu, mx, 2));
            float m_new = fmaxf(m_run[r], mx);
            float corr  = exp2f(m_run[r] - m_new);
            float ps = 0.f;
#pragma unroll
            for (int nb = 0; nb < 8; ++nb) {
                float p0 = exp2f(s[nb][2 * r] - m_new);
                float p1 = exp2f(s[nb][2 * r + 1] - m_new);
                s[nb][2 * r] = p0; s[nb][2 * r + 1] = p1;
                ps += p0 + p1;
            }
            ps += __shfl_xor_sync(0xffffffffu, ps, 1);
            ps += __shfl_xor_sync(0xffffffffu, ps, 2);
            l_run[r] = l_run[r] * corr + ps;
            m_run[r] = m_new;
#pragma unroll
            for (int nb = 0; nb < 8; ++nb) {
                acc_o[nb][2 * r]     *= corr;
                acc_o[nb][2 * r + 1] *= corr;
            }
        }

        // ---- P (fp16) to warp-private smem rows ----
        __syncwarp();
#pragma unroll
        for (int nb = 0; nb < 8; ++nb) {
            Ps[rbq * TST + nb * 4 + c]       = pack_h2(s[nb][0], s[nb][1]);
            Ps[(rbq + 8) * TST + nb * 4 + c] = pack_h2(s[nb][2], s[nb][3]);
        }
        __syncwarp();

        // ---- O += P V  (B from V^T: rows = d, k = s) ----
#pragma unroll
        for (int kk = 0; kk < 4; ++kk) {
            int ab = rbq * TST + kk * 8 + c;
            uint32_t a0 = Ps[ab], a1 = Ps[ab + 8 * TST];
            uint32_t a2 = Ps[ab + 4], a3 = Ps[ab + 8 * TST + 4];
#pragma unroll
            for (int nb = 0; nb < 8; ++nb) {
                int bb = (nb * 8 + g) * TST + kk * 8 + c;
                mma_f16(acc_o[nb], a0, a1, a2, a3, Vc[bb], Vc[bb + 4]);
            }
        }
    }

    // ---- write context (fp32) ----
#pragma unroll
    for (int r = 0; r < 2; ++r) {
        float inv = 1.f / l_run[r];
        int row = q0 + rbq + r * 8;
        size_t base = ((size_t)n * T + row) * 64;
#pragma unroll
        for (int nb = 0; nb < 8; ++nb) {
            float2 v2 = make_float2(acc_o[nb][2 * r] * inv, acc_o[nb][2 * r + 1] * inv);
            *(float2*)&g_Ctx[base + nb * 8 + 2 * c] = v2;
        }
    }
}

// ---------------------------------------------------------------------------
// Merge heads + residual + LayerNorm. One block (256 threads) per (b,t) row.
// ---------------------------------------------------------------------------
__global__ __launch_bounds__(256) void merge_ln_kernel(
    const float* __restrict__ qin,
    const float* __restrict__ gamma, const float* __restrict__ beta,
    float* __restrict__ out, int B, int T, int D, int depth)
{
    const int row = blockIdx.x;
    const int b = row / T, t = row % T;
    const int tid = threadIdx.x;

    float vals[4];
    float sum = 0.f, sq = 0.f;
#pragma unroll
    for (int u = 0; u < 4; ++u) {
        int cidx = tid + u * 256;
        int head = cidx / depth, dd = cidx % depth;
        float v = g_Ctx[(((size_t)head * B + b) * T + t) * depth + dd] +
                  qin[(size_t)row * D + cidx];
        vals[u] = v;
        sum += v;
        sq  += v * v;
    }
#pragma unroll
    for (int o = 16; o; o >>= 1) {
        sum += __shfl_xor_sync(0xffffffffu, sum, o);
        sq  += __shfl_xor_sync(0xffffffffu, sq, o);
    }
    __shared__ float s1[8], s2[8];
    int w = tid >> 5, l = tid & 31;
    if (l == 0) { s1[w] = sum; s2[w] = sq; }
    __syncthreads();
    if (w == 0) {
        sum = (l < 8) ? s1[l] : 0.f;
        sq  = (l < 8) ? s2[l] : 0.f;
#pragma unroll
        for (int o = 4; o; o >>= 1) {
            sum += __shfl_xor_sync(0xffffffffu, sum, o);
            sq  += __shfl_xor_sync(0xffffffffu, sq, o);
        }
        if (l == 0) { s1[0] = sum; s2[0] = sq; }
    }
    __syncthreads();
    sum = s1[0];
    sq  = s2[0];
    float mu  = sum / (float)D;
    float var = sq / (float)D - mu * mu;
    float inv = rsqrtf(var + 1e-5f);
#pragma unroll
    for (int u = 0; u < 4; ++u) {
        int cidx = tid + u * 256;
        out[(size_t)row * D + cidx] = (vals[u] - mu) * inv * gamma[cidx] + beta[cidx];
    }
}

// ---------------------------------------------------------------------------
extern "C" void kernel_launch(void* const* d_in, const int* in_sizes, int n_in,
                              void* d_out, int out_size)
{
    const float* q    = (const float*)d_in[0];
    const float* k    = (const float*)d_in[1];
    const float* v    = (const float*)d_in[2];
    const int*   mask = (const int*)d_in[3];
    const int*   caus = (const int*)d_in[4];
    // d_in[5] = edge_fea (unused)
    const float* wq = (const float*)d_in[6];
    const float* bq = (const float*)d_in[7];
    const float* wk = (const float*)d_in[8];
    const float* bk = (const float*)d_in[9];
    const float* wv = (const float*)d_in[10];
    const float* bv = (const float*)d_in[11];
    const float* gamma = (const float*)d_in[12];
    const float* beta  = (const float*)d_in[13];
    float* out = (float*)d_out;

    const int D  = in_sizes[7];      // bq length
    const int BT = in_sizes[3];      // mask length = B*T
    int T = 2048;
    if (BT % T != 0) T = BT;
    const int B = BT / T;
    const int depth = D / NUM_HEADS;
    const int nA = BT * D;
    const int nW = D * D;

    cudaFuncSetAttribute(gemm_f16_kernel, cudaFuncAttributeMaxDynamicSharedMemorySize,
                         GEMM_SMEM_BYTES);
    cudaFuncSetAttribute(attn_f16_kernel, cudaFuncAttributeMaxDynamicSharedMemorySize,
                         ATTN_SMEM_BYTES);

    long totalCvt = 3L * nA + 3L * nW;
    int cvtBlocks = (int)((totalCvt / 8 + 255) / 256);
    cvt_all_kernel<<<cvtBlocks, 256>>>(q, k, v, wq, wk, wv, nA, nW);

    dim3 gemm_grid(D / 128, BT / 128, 3);
    gemm_f16_kernel<<<gemm_grid, 256, GEMM_SMEM_BYTES>>>(bq, bk, bv, D, B, T, depth);

    dim3 attn_grid(T / 128, NUM_HEADS * B);
    attn_f16_kernel<<<attn_grid, 256, ATTN_SMEM_BYTES>>>(mask, caus, B, T);

    merge_ln_kernel<<<BT, 256>>>(q, gamma, beta, out, B, T, D, depth);
}

// round 7
// speedup vs baseline: 7.3306x; 1.1105x over previous
#include <cuda_runtime.h>
#include <cuda_fp16.h>
#include <math.h>
#include <stdint.h>

#define NUM_HEADS 16
#define LOG2E 1.4426950408889634f
#define SCALE2 (0.125f * LOG2E)
#define PADL2 (-6.196328e9f)     // PADV * LOG2E

// fp16 scratch
#define A_ELEMS 4194304          // BT*D = 4096*1024
#define W_ELEMS 1048576          // D*D
__device__ __half g_Aq[A_ELEMS];
__device__ __half g_Ak[A_ELEMS];
__device__ __half g_Av[A_ELEMS];
__device__ __half g_Wq[W_ELEMS];
__device__ __half g_Wk[W_ELEMS];
__device__ __half g_Wv[W_ELEMS];
__device__ __half g_Qh[A_ELEMS];   // [n][t][d] head-split
__device__ __half g_Kh[A_ELEMS];   // [n][t][d]
__device__ __half g_VhT[A_ELEMS];  // [n*64 + d][T]  (transposed)
__device__ float  g_Ctx[A_ELEMS];

// ---------------------------------------------------------------------------
// helpers
// ---------------------------------------------------------------------------
__device__ __forceinline__ uint32_t s2u(const void* p) {
    return (uint32_t)__cvta_generic_to_shared(p);
}
__device__ __forceinline__ void cpa16(uint32_t dst, const void* src) {
    asm volatile("cp.async.cg.shared.global [%0], [%1], 16;" :: "r"(dst), "l"(src));
}
__device__ __forceinline__ void cpa_commit() {
    asm volatile("cp.async.commit_group;" ::: "memory");
}
__device__ __forceinline__ void mma_f16(float* c,
                                        uint32_t a0, uint32_t a1, uint32_t a2, uint32_t a3,
                                        uint32_t b0, uint32_t b1) {
    asm volatile(
        "mma.sync.aligned.m16n8k16.row.col.f32.f16.f16.f32 "
        "{%0,%1,%2,%3}, {%4,%5,%6,%7}, {%8,%9}, {%0,%1,%2,%3};\n"
        : "+f"(c[0]), "+f"(c[1]), "+f"(c[2]), "+f"(c[3])
        : "r"(a0), "r"(a1), "r"(a2), "r"(a3), "r"(b0), "r"(b1));
}
__device__ __forceinline__ void ldsm4(uint32_t& r0, uint32_t& r1, uint32_t& r2,
                                      uint32_t& r3, uint32_t addr) {
    asm volatile("ldmatrix.sync.aligned.m8n8.x4.shared.b16 {%0,%1,%2,%3}, [%4];"
                 : "=r"(r0), "=r"(r1), "=r"(r2), "=r"(r3) : "r"(addr));
}
__device__ __forceinline__ uint32_t pack_h2(float lo, float hi) {
    half2 h = __floats2half2_rn(lo, hi);
    return *(uint32_t*)&h;
}

// ---------------------------------------------------------------------------
// One fused fp32 -> fp16 conversion kernel for q,k,v,wq,wk,wv.
// ---------------------------------------------------------------------------
__global__ __launch_bounds__(256) void cvt_all_kernel(
    const float* __restrict__ q, const float* __restrict__ k, const float* __restrict__ v,
    const float* __restrict__ wq, const float* __restrict__ wk, const float* __restrict__ wv,
    int nA, int nW)
{
    long i = ((long)blockIdx.x * 256 + threadIdx.x) * 8;
    const long total = 3L * nA + 3L * nW;
    if (i >= total) return;

    const float* src;
    __half* dst;
    long off;
    if (i < (long)nA)            { src = q;  dst = g_Aq; off = i; }
    else if (i < 2L * nA)        { src = k;  dst = g_Ak; off = i - nA; }
    else if (i < 3L * nA)        { src = v;  dst = g_Av; off = i - 2L * nA; }
    else if (i < 3L * nA + nW)   { src = wq; dst = g_Wq; off = i - 3L * nA; }
    else if (i < 3L * nA + 2L * nW) { src = wk; dst = g_Wk; off = i - 3L * nA - nW; }
    else                         { src = wv; dst = g_Wv; off = i - 3L * nA - 2L * nW; }

    float4 v0 = *(const float4*)(src + off);
    float4 v1 = *(const float4*)(src + off + 4);
    uint4 o;
    o.x = pack_h2(v0.x, v0.y);
    o.y = pack_h2(v0.z, v0.w);
    o.z = pack_h2(v1.x, v1.y);
    o.w = pack_h2(v1.z, v1.w);
    *(uint4*)(dst + off) = o;
}

// ---------------------------------------------------------------------------
// fp16 tensor-core GEMM, ldmatrix fragments: head_split(A @ W^T + bias).
// Block tile 128x128, BK=64, cp.async double buffered, 8 warps (4x2),
// warp tile 32x64. sel: 0=Q, 1=K, 2=V (transposed via smem).
// ---------------------------------------------------------------------------
#define GST32 36
#define GROWB 144                             // bytes per smem row
#define GBUF (128 * GST32)                    // u32 per buffer
#define GEMM_SMEM_BYTES (4 * GBUF * 4)        // 73728 B
#define TRST 136

__global__ __launch_bounds__(256, 2) void gemm_f16_kernel(
    const float* __restrict__ bq, const float* __restrict__ bk, const float* __restrict__ bv,
    int K, int B, int T, int depth)
{
    const int sel = blockIdx.z;
    const __half* A = (sel == 0) ? g_Aq : (sel == 1) ? g_Ak : g_Av;
    const __half* W = (sel == 0) ? g_Wq : (sel == 1) ? g_Wk : g_Wv;
    const float* bias = (sel == 0) ? bq : (sel == 1) ? bk : bv;

    extern __shared__ uint32_t gsm[];
    const uint32_t abase = s2u(gsm);
    const uint32_t bbase = abase + 2 * GBUF * 4;

    const int tid  = threadIdx.x;
    const int lane = tid & 31;
    const int warp = tid >> 5;
    const int wm   = (warp >> 1) * 32;
    const int wn   = (warp & 1) * 64;
    const int g    = lane >> 2;
    const int c    = lane & 3;
    const int cRow = blockIdx.y * 128;
    const int cCol = blockIdx.x * 128;

    // ldmatrix lane-address offsets (within a stage buffer)
    const int j  = lane >> 3;
    const int rr = lane & 7;
    // A-type (a0..a3 = rows{0,8} x k{0,8}): row += (j&1)*8, koff = (j>>1)*8
    const uint32_t aOffA = (uint32_t)((wm + ((j & 1) << 3) + rr) * GROWB + ((j >> 1) << 4));
    // B-type (pair of n-blocks): row += (j>>1)*8, koff = (j&1)*8
    const uint32_t bOffB = (uint32_t)((wn + ((j >> 1) << 3) + rr) * GROWB + ((j & 1) << 4));

    float acc[2][8][4];
#pragma unroll
    for (int mb = 0; mb < 2; ++mb)
#pragma unroll
        for (int nb = 0; nb < 8; ++nb)
#pragma unroll
            for (int jj = 0; jj < 4; ++jj) acc[mb][nb][jj] = 0.f;

    auto issue = [&](int k0, int s) {
        uint32_t ab = abase + (uint32_t)(s * GBUF) * 4u;
        uint32_t bb = bbase + (uint32_t)(s * GBUF) * 4u;
#pragma unroll
        for (int i = 0; i < 4; ++i) {
            int idx = tid + i * 256;
            int r = idx >> 3, ch = idx & 7;
            cpa16(ab + (uint32_t)(r * GROWB + ch * 16),
                  A + (size_t)(cRow + r) * K + k0 + ch * 8);
            cpa16(bb + (uint32_t)(r * GROWB + ch * 16),
                  W + (size_t)(cCol + r) * K + k0 + ch * 8);
        }
    };

    const int NT = K / 64;
    issue(0, 0);
    cpa_commit();

    for (int it = 0; it < NT; ++it) {
        const int cur = it & 1;
        if (it > 0) __syncthreads();
        if (it + 1 < NT) {
            issue((it + 1) * 64, cur ^ 1);
            cpa_commit();
            asm volatile("cp.async.wait_group 1;" ::: "memory");
        } else {
            asm volatile("cp.async.wait_group 0;" ::: "memory");
        }
        __syncthreads();

        const uint32_t aStage = abase + (uint32_t)(cur * GBUF) * 4u;
        const uint32_t bStage = bbase + (uint32_t)(cur * GBUF) * 4u;
#pragma unroll
        for (int kk = 0; kk < 4; ++kk) {
            uint32_t a[2][4];
            ldsm4(a[0][0], a[0][1], a[0][2], a[0][3], aStage + aOffA + kk * 32);
            ldsm4(a[1][0], a[1][1], a[1][2], a[1][3],
                  aStage + aOffA + 16 * GROWB + kk * 32);
#pragma unroll
            for (int p = 0; p < 4; ++p) {
                uint32_t b0, b1, b2, b3;
                ldsm4(b0, b1, b2, b3, bStage + bOffB + p * 16 * GROWB + kk * 32);
                mma_f16(acc[0][2 * p],     a[0][0], a[0][1], a[0][2], a[0][3], b0, b1);
                mma_f16(acc[1][2 * p],     a[1][0], a[1][1], a[1][2], a[1][3], b0, b1);
                mma_f16(acc[0][2 * p + 1], a[0][0], a[0][1], a[0][2], a[0][3], b2, b3);
                mma_f16(acc[1][2 * p + 1], a[1][0], a[1][1], a[1][2], a[1][3], b2, b3);
            }
        }
    }

    if (sel < 2) {
        __half* dst = (sel == 0) ? g_Qh : g_Kh;
#pragma unroll
        for (int mb = 0; mb < 2; ++mb) {
#pragma unroll
            for (int nb = 0; nb < 8; ++nb) {
                int col0 = cCol + wn + nb * 8 + 2 * c;
                float b0v = bias[col0], b1v = bias[col0 + 1];
                int head = col0 / depth, dd = col0 % depth;
#pragma unroll
                for (int rw = 0; rw < 2; ++rw) {
                    int m = cRow + wm + mb * 16 + g + rw * 8;
                    int bi = m / T, t = m % T;
                    uint32_t p = pack_h2(acc[mb][nb][rw * 2 + 0] + b0v,
                                         acc[mb][nb][rw * 2 + 1] + b1v);
                    *(uint32_t*)(dst + (((size_t)head * B + bi) * T + t) * depth + dd) = p;
                }
            }
        }
    } else {
        __syncthreads();
        __half* tb = (__half*)gsm;     // [128 cols][TRST]
#pragma unroll
        for (int mb = 0; mb < 2; ++mb) {
#pragma unroll
            for (int nb = 0; nb < 8; ++nb) {
                int col0 = wn + nb * 8 + 2 * c;
                float b0v = bias[cCol + col0], b1v = bias[cCol + col0 + 1];
#pragma unroll
                for (int rw = 0; rw < 2; ++rw) {
                    int m = wm + mb * 16 + g + rw * 8;
                    tb[col0 * TRST + m]       = __float2half_rn(acc[mb][nb][rw * 2 + 0] + b0v);
                    tb[(col0 + 1) * TRST + m] = __float2half_rn(acc[mb][nb][rw * 2 + 1] + b1v);
                }
            }
        }
        __syncthreads();
        const int bi = cRow / T;
        const int t0 = cRow % T;
#pragma unroll
        for (int i = 0; i < 8; ++i) {
            int idx = tid + i * 256;
            int dl = idx >> 4, c16 = idx & 15;
            int dg = cCol + dl;
            size_t vrow = ((size_t)(dg >> 6) * B + bi) * 64 + (dg & 63);
            *(uint4*)(g_VhT + vrow * T + t0 + c16 * 8) =
                *(const uint4*)(tb + dl * TRST + c16 * 8);
        }
    }
}

// ---------------------------------------------------------------------------
// Flash attention, fp16 m16n8k16, ldmatrix fragments, P kept in registers.
// 128-query tiles, 8 warps, cp.async double-buffered K/V^T/mask, exp2 softmax.
// Key mask row = n / NUM_HEADS (reference's batch-interleaved repeat).
// ---------------------------------------------------------------------------
#define TST 36
#define QTILE32 (128 * TST)      // 4608
#define KTILE32 (64 * TST)       // 2304
#define OFF_K  QTILE32
#define OFF_V  (QTILE32 + 2 * KTILE32)
#define OFF_MK (QTILE32 + 4 * KTILE32)
#define ATTN_SMEM_BYTES ((OFF_MK + 128) * 4)    // 55808 B

__global__ __launch_bounds__(256) void attn_f16_kernel(
    const int* __restrict__ mask, const int* __restrict__ causality,
    int B, int T)
{
    extern __shared__ uint32_t sm[];
    int* maskS = (int*)(sm + OFF_MK);

    const int n    = blockIdx.y;
    const int q0   = blockIdx.x * 128;
    const int tid  = threadIdx.x;
    const int lane = tid & 31;
    const int warp = tid >> 5;
    const int g    = lane >> 2;
    const int c    = lane & 3;
    const int mrow = n / NUM_HEADS;
    const int caus = causality[0];
    const int rbq  = warp * 16 + g;

    const uint32_t qb = s2u(sm);
    const uint32_t kb = qb + OFF_K * 4;
    const uint32_t vb = qb + OFF_V * 4;

    const int j  = lane >> 3;
    const int rr = lane & 7;
    const uint32_t aOffQ = (uint32_t)((warp * 16 + ((j & 1) << 3) + rr) * GROWB +
                                      ((j >> 1) << 4));
    const uint32_t bOff  = (uint32_t)((((j >> 1) << 3) + rr) * GROWB + ((j & 1) << 4));

    // Q tile: 128 rows x 64 halves
    {
        const __half* src = g_Qh + ((size_t)n * T + q0) * 64;
#pragma unroll
        for (int i = 0; i < 4; ++i) {
            int idx = tid + i * 256;
            int r = idx >> 3, ch = idx & 7;
            cpa16(qb + (uint32_t)(r * GROWB + ch * 16), src + (size_t)r * 64 + ch * 8);
        }
    }

    auto issue_kv = [&](int t, int s) {
        const __half* ksrc = g_Kh + ((size_t)n * T + t * 64) * 64;
        const __half* vsrc = g_VhT + (size_t)n * 64 * T + t * 64;
        uint32_t kdst = kb + (uint32_t)(s * KTILE32) * 4u;
        uint32_t vdst = vb + (uint32_t)(s * KTILE32) * 4u;
#pragma unroll
        for (int i = 0; i < 2; ++i) {
            int idx = tid + i * 256;
            int r = idx >> 3, ch = idx & 7;
            cpa16(kdst + (uint32_t)(r * GROWB + ch * 16), ksrc + (size_t)r * 64 + ch * 8);
            cpa16(vdst + (uint32_t)(r * GROWB + ch * 16), vsrc + (size_t)r * T + ch * 8);
        }
        if (tid < 16)
            cpa16(s2u(maskS) + (uint32_t)(s * 64 + tid * 4) * 4u,
                  mask + (size_t)mrow * T + t * 64 + tid * 4);
    };

    const int NT = T / 64;
    issue_kv(0, 0);
    cpa_commit();

    float m_run[2] = {-INFINITY, -INFINITY};
    float l_run[2] = {0.f, 0.f};
    float acc_o[8][4];
#pragma unroll
    for (int nb = 0; nb < 8; ++nb)
#pragma unroll
        for (int jj = 0; jj < 4; ++jj) acc_o[nb][jj] = 0.f;

    for (int t = 0; t < NT; ++t) {
        const int cur = t & 1;
        if (t > 0) __syncthreads();
        if (t + 1 < NT) {
            issue_kv(t + 1, cur ^ 1);
            cpa_commit();
            asm volatile("cp.async.wait_group 1;" ::: "memory");
        } else {
            asm volatile("cp.async.wait_group 0;" ::: "memory");
        }
        __syncthreads();

        const uint32_t kStage = kb + (uint32_t)(cur * KTILE32) * 4u;
        const uint32_t vStage = vb + (uint32_t)(cur * KTILE32) * 4u;
        const int* mk = maskS + cur * 64;

        // ---- S = Q K^T ----
        float s[8][4];
#pragma unroll
        for (int nb = 0; nb < 8; ++nb)
#pragma unroll
            for (int jj = 0; jj < 4; ++jj) s[nb][jj] = 0.f;

#pragma unroll
        for (int kk = 0; kk < 4; ++kk) {
            uint32_t a0, a1, a2, a3;
            ldsm4(a0, a1, a2, a3, qb + aOffQ + kk * 32);
#pragma unroll
            for (int p = 0; p < 4; ++p) {
                uint32_t b0, b1, b2, b3;
                ldsm4(b0, b1, b2, b3, kStage + bOff + p * 16 * GROWB + kk * 32);
                mma_f16(s[2 * p],     a0, a1, a2, a3, b0, b1);
                mma_f16(s[2 * p + 1], a0, a1, a2, a3, b2, b3);
            }
        }

        // ---- scale (exp2 domain) + key mask + optional causal ----
#pragma unroll
        for (int nb = 0; nb < 8; ++nb) {
#pragma unroll
            for (int jj = 0; jj < 4; ++jj) {
                int col = nb * 8 + 2 * c + (jj & 1);
                float v = fmaf(s[nb][jj], SCALE2, mk[col] ? PADL2 : 0.f);
                if (caus) {
                    int row = rbq + ((jj >> 1) << 3);
                    if ((t * 64 + col) > (q0 + row)) v = PADL2;
                }
                s[nb][jj] = v;
            }
        }

        // ---- online softmax (2 rows/thread; stats across quad lanes) ----
#pragma unroll
        for (int r = 0; r < 2; ++r) {
            float mx = -INFINITY;
#pragma unroll
            for (int nb = 0; nb < 8; ++nb)
                mx = fmaxf(mx, fmaxf(s[nb][2 * r], s[nb][2 * r + 1]));
            mx = fmaxf(mx, __shfl_xor_sync(0xffffffffu, mx, 1));
            mx = fmaxf(mx, __shfl_xor_sync(0xffffffffu, mx, 2));
            float m_new = fmaxf(m_run[r], mx);
            float corr  = exp2f(m_run[r] - m_new);
            float ps = 0.f;
#pragma unroll
            for (int nb = 0; nb < 8; ++nb) {
                float p0 = exp2f(s[nb][2 * r] - m_new);
                float p1 = exp2f(s[nb][2 * r + 1] - m_new);
                s[nb][2 * r] = p0; s[nb][2 * r + 1] = p1;
                ps += p0 + p1;
            }
            ps += __shfl_xor_sync(0xffffffffu, ps, 1);
            ps += __shfl_xor_sync(0xffffffffu, ps, 2);
            l_run[r] = l_run[r] * corr + ps;
            m_run[r] = m_new;
#pragma unroll
            for (int nb = 0; nb < 8; ++nb) {
                acc_o[nb][2 * r]     *= corr;
                acc_o[nb][2 * r + 1] *= corr;
            }
        }

        // ---- O += P V : P's C-fragment layout == A-fragment layout ----
#pragma unroll
        for (int kk = 0; kk < 4; ++kk) {
            uint32_t a0 = pack_h2(s[2 * kk][0],     s[2 * kk][1]);
            uint32_t a1 = pack_h2(s[2 * kk][2],     s[2 * kk][3]);
            uint32_t a2 = pack_h2(s[2 * kk + 1][0], s[2 * kk + 1][1]);
            uint32_t a3 = pack_h2(s[2 * kk + 1][2], s[2 * kk + 1][3]);
#pragma unroll
            for (int p = 0; p < 4; ++p) {
                uint32_t b0, b1, b2, b3;
                ldsm4(b0, b1, b2, b3, vStage + bOff + p * 16 * GROWB + kk * 32);
                mma_f16(acc_o[2 * p],     a0, a1, a2, a3, b0, b1);
                mma_f16(acc_o[2 * p + 1], a0, a1, a2, a3, b2, b3);
            }
        }
    }

    // ---- write context (fp32) ----
#pragma unroll
    for (int r = 0; r < 2; ++r) {
        float inv = 1.f / l_run[r];
        int row = q0 + rbq + r * 8;
        size_t base = ((size_t)n * T + row) * 64;
#pragma unroll
        for (int nb = 0; nb < 8; ++nb) {
            float2 v2 = make_float2(acc_o[nb][2 * r] * inv, acc_o[nb][2 * r + 1] * inv);
            *(float2*)&g_Ctx[base + nb * 8 + 2 * c] = v2;
        }
    }
}

// ---------------------------------------------------------------------------
// Merge heads + residual + LayerNorm. One block (256 threads) per (b,t) row.
// ---------------------------------------------------------------------------
__global__ __launch_bounds__(256) void merge_ln_kernel(
    const float* __restrict__ qin,
    const float* __restrict__ gamma, const float* __restrict__ beta,
    float* __restrict__ out, int B, int T, int D, int depth)
{
    const int row = blockIdx.x;
    const int b = row / T, t = row % T;
    const int tid = threadIdx.x;

    float vals[4];
    float sum = 0.f, sq = 0.f;
#pragma unroll
    for (int u = 0; u < 4; ++u) {
        int cidx = tid + u * 256;
        int head = cidx / depth, dd = cidx % depth;
        float v = g_Ctx[(((size_t)head * B + b) * T + t) * depth + dd] +
                  qin[(size_t)row * D + cidx];
        vals[u] = v;
        sum += v;
        sq  += v * v;
    }
#pragma unroll
    for (int o = 16; o; o >>= 1) {
        sum += __shfl_xor_sync(0xffffffffu, sum, o);
        sq  += __shfl_xor_sync(0xffffffffu, sq, o);
    }
    __shared__ float s1[8], s2[8];
    int w = tid >> 5, l = tid & 31;
    if (l == 0) { s1[w] = sum; s2[w] = sq; }
    __syncthreads();
    if (w == 0) {
        sum = (l < 8) ? s1[l] : 0.f;
        sq  = (l < 8) ? s2[l] : 0.f;
#pragma unroll
        for (int o = 4; o; o >>= 1) {
            sum += __shfl_xor_sync(0xffffffffu, sum, o);
            sq  += __shfl_xor_sync(0xffffffffu, sq, o);
        }
        if (l == 0) { s1[0] = sum; s2[0] = sq; }
    }
    __syncthreads();
    sum = s1[0];
    sq  = s2[0];
    float mu  = sum / (float)D;
    float var = sq / (float)D - mu * mu;
    float inv = rsqrtf(var + 1e-5f);
#pragma unroll
    for (int u = 0; u < 4; ++u) {
        int cidx = tid + u * 256;
        out[(size_t)row * D + cidx] = (vals[u] - mu) * inv * gamma[cidx] + beta[cidx];
    }
}

// ---------------------------------------------------------------------------
extern "C" void kernel_launch(void* const* d_in, const int* in_sizes, int n_in,
                              void* d_out, int out_size)
{
    const float* q    = (const float*)d_in[0];
    const float* k    = (const float*)d_in[1];
    const float* v    = (const float*)d_in[2];
    const int*   mask = (const int*)d_in[3];
    const int*   caus = (const int*)d_in[4];
    // d_in[5] = edge_fea (unused)
    const float* wq = (const float*)d_in[6];
    const float* bq = (const float*)d_in[7];
    const float* wk = (const float*)d_in[8];
    const float* bk = (const float*)d_in[9];
    const float* wv = (const float*)d_in[10];
    const float* bv = (const float*)d_in[11];
    const float* gamma = (const float*)d_in[12];
    const float* beta  = (const float*)d_in[13];
    float* out = (float*)d_out;

    const int D  = in_sizes[7];      // bq length
    const int BT = in_sizes[3];      // mask length = B*T
    int T = 2048;
    if (BT % T != 0) T = BT;
    const int B = BT / T;
    const int depth = D / NUM_HEADS;
    const int nA = BT * D;
    const int nW = D * D;

    cudaFuncSetAttribute(gemm_f16_kernel, cudaFuncAttributeMaxDynamicSharedMemorySize,
                         GEMM_SMEM_BYTES);
    cudaFuncSetAttribute(attn_f16_kernel, cudaFuncAttributeMaxDynamicSharedMemorySize,
                         ATTN_SMEM_BYTES);

    long totalCvt = 3L * nA + 3L * nW;
    int cvtBlocks = (int)((totalCvt / 8 + 255) / 256);
    cvt_all_kernel<<<cvtBlocks, 256>>>(q, k, v, wq, wk, wv, nA, nW);

    dim3 gemm_grid(D / 128, BT / 128, 3);
    gemm_f16_kernel<<<gemm_grid, 256, GEMM_SMEM_BYTES>>>(bq, bk, bv, D, B, T, depth);

    dim3 attn_grid(T / 128, NUM_HEADS * B);
    attn_f16_kernel<<<attn_grid, 256, ATTN_SMEM_BYTES>>>(mask, caus, B, T);

    merge_ln_kernel<<<BT, 256>>>(q, gamma, beta, out, B, T, D, depth);
}

// round 8
// speedup vs baseline: 7.4145x; 1.0114x over previous
#include <cuda_runtime.h>
#include <cuda_fp16.h>
#include <math.h>
#include <stdint.h>

#define NUM_HEADS 16
#define LOG2E 1.4426950408889634f
#define SCALE2 (0.125f * LOG2E)
#define PADL2 (-6.196328e9f)     // PADV * LOG2E

// fp16 scratch
#define A_ELEMS 4194304          // BT*D = 4096*1024
#define W_ELEMS 1048576          // D*D
__device__ __half g_Aq[A_ELEMS];
__device__ __half g_Ak[A_ELEMS];
__device__ __half g_Av[A_ELEMS];
__device__ __half g_Wq[W_ELEMS];
__device__ __half g_Wk[W_ELEMS];
__device__ __half g_Wv[W_ELEMS];
__device__ __half g_Qh[A_ELEMS];    // [n][t][d] head-split
__device__ __half g_Kh[A_ELEMS];    // [n][t][d]
__device__ __half g_VhT[A_ELEMS];   // [n*64 + d][T]  (transposed)
__device__ __half g_Ctx16[A_ELEMS]; // attention output, fp16

// ---------------------------------------------------------------------------
// helpers
// ---------------------------------------------------------------------------
__device__ __forceinline__ uint32_t s2u(const void* p) {
    return (uint32_t)__cvta_generic_to_shared(p);
}
__device__ __forceinline__ void cpa16(uint32_t dst, const void* src) {
    asm volatile("cp.async.cg.shared.global [%0], [%1], 16;" :: "r"(dst), "l"(src));
}
__device__ __forceinline__ void cpa_commit() {
    asm volatile("cp.async.commit_group;" ::: "memory");
}
__device__ __forceinline__ void mma_f16(float* c,
                                        uint32_t a0, uint32_t a1, uint32_t a2, uint32_t a3,
                                        uint32_t b0, uint32_t b1) {
    asm volatile(
        "mma.sync.aligned.m16n8k16.row.col.f32.f16.f16.f32 "
        "{%0,%1,%2,%3}, {%4,%5,%6,%7}, {%8,%9}, {%0,%1,%2,%3};\n"
        : "+f"(c[0]), "+f"(c[1]), "+f"(c[2]), "+f"(c[3])
        : "r"(a0), "r"(a1), "r"(a2), "r"(a3), "r"(b0), "r"(b1));
}
__device__ __forceinline__ void ldsm4(uint32_t& r0, uint32_t& r1, uint32_t& r2,
                                      uint32_t& r3, uint32_t addr) {
    asm volatile("ldmatrix.sync.aligned.m8n8.x4.shared.b16 {%0,%1,%2,%3}, [%4];"
                 : "=r"(r0), "=r"(r1), "=r"(r2), "=r"(r3) : "r"(addr));
}
__device__ __forceinline__ uint32_t pack_h2(float lo, float hi) {
    half2 h = __floats2half2_rn(lo, hi);
    return *(uint32_t*)&h;
}

// ---------------------------------------------------------------------------
// One fused fp32 -> fp16 conversion kernel for q,k,v,wq,wk,wv.
// ---------------------------------------------------------------------------
__global__ __launch_bounds__(256) void cvt_all_kernel(
    const float* __restrict__ q, const float* __restrict__ k, const float* __restrict__ v,
    const float* __restrict__ wq, const float* __restrict__ wk, const float* __restrict__ wv,
    int nA, int nW)
{
    long i = ((long)blockIdx.x * 256 + threadIdx.x) * 8;
    const long total = 3L * nA + 3L * nW;
    if (i >= total) return;

    const float* src;
    __half* dst;
    long off;
    if (i < (long)nA)            { src = q;  dst = g_Aq; off = i; }
    else if (i < 2L * nA)        { src = k;  dst = g_Ak; off = i - nA; }
    else if (i < 3L * nA)        { src = v;  dst = g_Av; off = i - 2L * nA; }
    else if (i < 3L * nA + nW)   { src = wq; dst = g_Wq; off = i - 3L * nA; }
    else if (i < 3L * nA + 2L * nW) { src = wk; dst = g_Wk; off = i - 3L * nA - nW; }
    else                         { src = wv; dst = g_Wv; off = i - 3L * nA - 2L * nW; }

    float4 v0 = *(const float4*)(src + off);
    float4 v1 = *(const float4*)(src + off + 4);
    uint4 o;
    o.x = pack_h2(v0.x, v0.y);
    o.y = pack_h2(v0.z, v0.w);
    o.z = pack_h2(v1.x, v1.y);
    o.w = pack_h2(v1.z, v1.w);
    *(uint4*)(dst + off) = o;
}

// ---------------------------------------------------------------------------
// fp16 tensor-core GEMM, ldmatrix fragments, 3-stage cp.async pipeline
// (one __syncthreads per K-tile). Block tile 128x128, BK=64, 8 warps (4x2),
// warp tile 32x64. sel: 0=Q, 1=K, 2=V (transposed via smem).
// ---------------------------------------------------------------------------
#define GROWB 144                             // bytes per smem row
#define GSTAGEB (256 * GROWB)                 // A(128 rows)+B(128 rows) = 36864 B
#define GEMM_SMEM_BYTES (3 * GSTAGEB)         // 110592 B
#define TRST 136

__global__ __launch_bounds__(256, 2) void gemm_f16_kernel(
    const float* __restrict__ bq, const float* __restrict__ bk, const float* __restrict__ bv,
    int K, int B, int T, int depth)
{
    const int sel = blockIdx.z;
    const __half* A = (sel == 0) ? g_Aq : (sel == 1) ? g_Ak : g_Av;
    const __half* W = (sel == 0) ? g_Wq : (sel == 1) ? g_Wk : g_Wv;
    const float* bias = (sel == 0) ? bq : (sel == 1) ? bk : bv;

    extern __shared__ uint32_t gsm[];
    const uint32_t sbase = s2u(gsm);

    const int tid  = threadIdx.x;
    const int lane = tid & 31;
    const int warp = tid >> 5;
    const int wm   = (warp >> 1) * 32;
    const int wn   = (warp & 1) * 64;
    const int g    = lane >> 2;
    const int c    = lane & 3;
    const int cRow = blockIdx.y * 128;
    const int cCol = blockIdx.x * 128;

    const int j  = lane >> 3;
    const int rr = lane & 7;
    const uint32_t aOffA = (uint32_t)((wm + ((j & 1) << 3) + rr) * GROWB + ((j >> 1) << 4));
    const uint32_t bOffB = (uint32_t)((wn + ((j >> 1) << 3) + rr) * GROWB + ((j & 1) << 4));

    float acc[2][8][4];
#pragma unroll
    for (int mb = 0; mb < 2; ++mb)
#pragma unroll
        for (int nb = 0; nb < 8; ++nb)
#pragma unroll
            for (int jj = 0; jj < 4; ++jj) acc[mb][nb][jj] = 0.f;

    auto issue = [&](int k0, int s) {
        uint32_t ab = sbase + (uint32_t)(s * GSTAGEB);
        uint32_t bb = ab + 128 * GROWB;
#pragma unroll
        for (int i = 0; i < 4; ++i) {
            int idx = tid + i * 256;
            int r = idx >> 3, ch = idx & 7;
            cpa16(ab + (uint32_t)(r * GROWB + ch * 16),
                  A + (size_t)(cRow + r) * K + k0 + ch * 8);
            cpa16(bb + (uint32_t)(r * GROWB + ch * 16),
                  W + (size_t)(cCol + r) * K + k0 + ch * 8);
        }
        cpa_commit();
    };

    const int NK = K / 64;
    issue(0, 0);
    if (NK > 1) issue(64, 1);

    for (int it = 0; it < NK; ++it) {
        if (it + 1 < NK)
            asm volatile("cp.async.wait_group 1;" ::: "memory");
        else
            asm volatile("cp.async.wait_group 0;" ::: "memory");
        __syncthreads();
        if (it + 2 < NK) issue((it + 2) * 64, (it + 2) % 3);

        const uint32_t aStage = sbase + (uint32_t)((it % 3) * GSTAGEB);
        const uint32_t bStage = aStage + 128 * GROWB;
#pragma unroll
        for (int kk = 0; kk < 4; ++kk) {
            uint32_t a[2][4];
            ldsm4(a[0][0], a[0][1], a[0][2], a[0][3], aStage + aOffA + kk * 32);
            ldsm4(a[1][0], a[1][1], a[1][2], a[1][3],
                  aStage + aOffA + 16 * GROWB + kk * 32);
#pragma unroll
            for (int p = 0; p < 4; ++p) {
                uint32_t b0, b1, b2, b3;
                ldsm4(b0, b1, b2, b3, bStage + bOffB + p * 16 * GROWB + kk * 32);
                mma_f16(acc[0][2 * p],     a[0][0], a[0][1], a[0][2], a[0][3], b0, b1);
                mma_f16(acc[1][2 * p],     a[1][0], a[1][1], a[1][2], a[1][3], b0, b1);
                mma_f16(acc[0][2 * p + 1], a[0][0], a[0][1], a[0][2], a[0][3], b2, b3);
                mma_f16(acc[1][2 * p + 1], a[1][0], a[1][1], a[1][2], a[1][3], b2, b3);
            }
        }
    }

    if (sel < 2) {
        __half* dst = (sel == 0) ? g_Qh : g_Kh;
#pragma unroll
        for (int mb = 0; mb < 2; ++mb) {
#pragma unroll
            for (int nb = 0; nb < 8; ++nb) {
                int col0 = cCol + wn + nb * 8 + 2 * c;
                float b0v = bias[col0], b1v = bias[col0 + 1];
                int head = col0 / depth, dd = col0 % depth;
#pragma unroll
                for (int rw = 0; rw < 2; ++rw) {
                    int m = cRow + wm + mb * 16 + g + rw * 8;
                    int bi = m / T, t = m % T;
                    uint32_t p = pack_h2(acc[mb][nb][rw * 2 + 0] + b0v,
                                         acc[mb][nb][rw * 2 + 1] + b1v);
                    *(uint32_t*)(dst + (((size_t)head * B + bi) * T + t) * depth + dd) = p;
                }
            }
        }
    } else {
        __syncthreads();
        __half* tb = (__half*)gsm;     // [128 cols][TRST]
#pragma unroll
        for (int mb = 0; mb < 2; ++mb) {
#pragma unroll
            for (int nb = 0; nb < 8; ++nb) {
                int col0 = wn + nb * 8 + 2 * c;
                float b0v = bias[cCol + col0], b1v = bias[cCol + col0 + 1];
#pragma unroll
                for (int rw = 0; rw < 2; ++rw) {
                    int m = wm + mb * 16 + g + rw * 8;
                    tb[col0 * TRST + m]       = __float2half_rn(acc[mb][nb][rw * 2 + 0] + b0v);
                    tb[(col0 + 1) * TRST + m] = __float2half_rn(acc[mb][nb][rw * 2 + 1] + b1v);
                }
            }
        }
        __syncthreads();
        const int bi = cRow / T;
        const int t0 = cRow % T;
#pragma unroll
        for (int i = 0; i < 8; ++i) {
            int idx = tid + i * 256;
            int dl = idx >> 4, c16 = idx & 15;
            int dg = cCol + dl;
            size_t vrow = ((size_t)(dg >> 6) * B + bi) * 64 + (dg & 63);
            *(uint4*)(g_VhT + vrow * T + t0 + c16 * 8) =
                *(const uint4*)(tb + dl * TRST + c16 * 8);
        }
    }
}

// ---------------------------------------------------------------------------
// Flash attention, fp16 m16n8k16, ldmatrix fragments, P in registers,
// 3-stage cp.async pipeline (one __syncthreads per key tile), exp2 softmax.
// 128-query tiles, 8 warps. Key mask row = n / NUM_HEADS.
// smem: Q (128x144B) | 3 stages of [K 64x144B | V 64x144B] | 3x mask(256B)
// ---------------------------------------------------------------------------
#define QBYTES (128 * GROWB)                   // 18432
#define ASTAGEB (128 * GROWB)                  // K+V = 18432
#define OFF_STG QBYTES
#define OFF_MK  (QBYTES + 3 * ASTAGEB)         // 73728
#define ATTN_SMEM_BYTES (OFF_MK + 3 * 256)     // 74496 B

__global__ __launch_bounds__(256) void attn_f16_kernel(
    const int* __restrict__ mask, const int* __restrict__ causality,
    int B, int T)
{
    extern __shared__ uint32_t sm[];

    const int n    = blockIdx.y;
    const int q0   = blockIdx.x * 128;
    const int tid  = threadIdx.x;
    const int lane = tid & 31;
    const int warp = tid >> 5;
    const int g    = lane >> 2;
    const int c    = lane & 3;
    const int mrow = n / NUM_HEADS;
    const int caus = causality[0];
    const int rbq  = warp * 16 + g;

    const uint32_t qb = s2u(sm);

    const int j  = lane >> 3;
    const int rr = lane & 7;
    const uint32_t aOffQ = (uint32_t)((warp * 16 + ((j & 1) << 3) + rr) * GROWB +
                                      ((j >> 1) << 4));
    const uint32_t bOff  = (uint32_t)((((j >> 1) << 3) + rr) * GROWB + ((j & 1) << 4));

    // Q tile: 128 rows x 64 halves
    {
        const __half* src = g_Qh + ((size_t)n * T + q0) * 64;
#pragma unroll
        for (int i = 0; i < 4; ++i) {
            int idx = tid + i * 256;
            int r = idx >> 3, ch = idx & 7;
            cpa16(qb + (uint32_t)(r * GROWB + ch * 16), src + (size_t)r * 64 + ch * 8);
        }
    }

    auto issue_kv = [&](int t, int s) {
        const __half* ksrc = g_Kh + ((size_t)n * T + t * 64) * 64;
        const __half* vsrc = g_VhT + (size_t)n * 64 * T + t * 64;
        uint32_t kdst = qb + OFF_STG + (uint32_t)(s * ASTAGEB);
        uint32_t vdst = kdst + 64 * GROWB;
#pragma unroll
        for (int i = 0; i < 2; ++i) {
            int idx = tid + i * 256;
            int r = idx >> 3, ch = idx & 7;
            cpa16(kdst + (uint32_t)(r * GROWB + ch * 16), ksrc + (size_t)r * 64 + ch * 8);
            cpa16(vdst + (uint32_t)(r * GROWB + ch * 16), vsrc + (size_t)r * T + ch * 8);
        }
        if (tid < 16)
            cpa16(qb + OFF_MK + (uint32_t)(s * 256 + tid * 16),
                  mask + (size_t)mrow * T + t * 64 + tid * 4);
        cpa_commit();
    };

    const int NT = T / 64;
    issue_kv(0, 0);
    if (NT > 1) issue_kv(1, 1);

    float m_run[2] = {-INFINITY, -INFINITY};
    float l_run[2] = {0.f, 0.f};
    float acc_o[8][4];
#pragma unroll
    for (int nb = 0; nb < 8; ++nb)
#pragma unroll
        for (int jj = 0; jj < 4; ++jj) acc_o[nb][jj] = 0.f;

    for (int t = 0; t < NT; ++t) {
        if (t + 1 < NT)
            asm volatile("cp.async.wait_group 1;" ::: "memory");
        else
            asm volatile("cp.async.wait_group 0;" ::: "memory");
        __syncthreads();
        if (t + 2 < NT) issue_kv(t + 2, (t + 2) % 3);

        const int st = t % 3;
        const uint32_t kStage = qb + OFF_STG + (uint32_t)(st * ASTAGEB);
        const uint32_t vStage = kStage + 64 * GROWB;
        const int* mk = (const int*)((const char*)sm + OFF_MK + st * 256);

        // ---- S = Q K^T ----
        float s[8][4];
#pragma unroll
        for (int nb = 0; nb < 8; ++nb)
#pragma unroll
            for (int jj = 0; jj < 4; ++jj) s[nb][jj] = 0.f;

#pragma unroll
        for (int kk = 0; kk < 4; ++kk) {
            uint32_t a0, a1, a2, a3;
            ldsm4(a0, a1, a2, a3, qb + aOffQ + kk * 32);
#pragma unroll
            for (int p = 0; p < 4; ++p) {
                uint32_t b0, b1, b2, b3;
                ldsm4(b0, b1, b2, b3, kStage + bOff + p * 16 * GROWB + kk * 32);
                mma_f16(s[2 * p],     a0, a1, a2, a3, b0, b1);
                mma_f16(s[2 * p + 1], a0, a1, a2, a3, b2, b3);
            }
        }

        // ---- scale (exp2 domain) + key mask + optional causal ----
#pragma unroll
        for (int nb = 0; nb < 8; ++nb) {
#pragma unroll
            for (int jj = 0; jj < 4; ++jj) {
                int col = nb * 8 + 2 * c + (jj & 1);
                float v = fmaf(s[nb][jj], SCALE2, mk[col] ? PADL2 : 0.f);
                if (caus) {
                    int row = rbq + ((jj >> 1) << 3);
                    if ((t * 64 + col) > (q0 + row)) v = PADL2;
                }
                s[nb][jj] = v;
            }
        }

        // ---- online softmax (2 rows/thread; stats across quad lanes) ----
#pragma unroll
        for (int r = 0; r < 2; ++r) {
            float mx = -INFINITY;
#pragma unroll
            for (int nb = 0; nb < 8; ++nb)
                mx = fmaxf(mx, fmaxf(s[nb][2 * r], s[nb][2 * r + 1]));
            mx = fmaxf(mx, __shfl_xor_sync(0xffffffffu, mx, 1));
            mx = fmaxf(mx, __shfl_xor_sync(0xffffffffu, mx, 2));
            float m_new = fmaxf(m_run[r], mx);
            float corr  = exp2f(m_run[r] - m_new);
            float ps = 0.f;
#pragma unroll
            for (int nb = 0; nb < 8; ++nb) {
                float p0 = exp2f(s[nb][2 * r] - m_new);
                float p1 = exp2f(s[nb][2 * r + 1] - m_new);
                s[nb][2 * r] = p0; s[nb][2 * r + 1] = p1;
                ps += p0 + p1;
            }
            ps += __shfl_xor_sync(0xffffffffu, ps, 1);
            ps += __shfl_xor_sync(0xffffffffu, ps, 2);
            l_run[r] = l_run[r] * corr + ps;
            m_run[r] = m_new;
#pragma unroll
            for (int nb = 0; nb < 8; ++nb) {
                acc_o[nb][2 * r]     *= corr;
                acc_o[nb][2 * r + 1] *= corr;
            }
        }

        // ---- O += P V : P's C-fragment layout == A-fragment layout ----
#pragma unroll
        for (int kk = 0; kk < 4; ++kk) {
            uint32_t a0 = pack_h2(s[2 * kk][0],     s[2 * kk][1]);
            uint32_t a1 = pack_h2(s[2 * kk][2],     s[2 * kk][3]);
            uint32_t a2 = pack_h2(s[2 * kk + 1][0], s[2 * kk + 1][1]);
            uint32_t a3 = pack_h2(s[2 * kk + 1][2], s[2 * kk + 1][3]);
#pragma unroll
            for (int p = 0; p < 4; ++p) {
                uint32_t b0, b1, b2, b3;
                ldsm4(b0, b1, b2, b3, vStage + bOff + p * 16 * GROWB + kk * 32);
                mma_f16(acc_o[2 * p],     a0, a1, a2, a3, b0, b1);
                mma_f16(acc_o[2 * p + 1], a0, a1, a2, a3, b2, b3);
            }
        }
    }

    // ---- write context (fp16) ----
#pragma unroll
    for (int r = 0; r < 2; ++r) {
        float inv = 1.f / l_run[r];
        int row = q0 + rbq + r * 8;
        size_t base = ((size_t)n * T + row) * 64;
#pragma unroll
        for (int nb = 0; nb < 8; ++nb) {
            *(uint32_t*)(g_Ctx16 + base + nb * 8 + 2 * c) =
                pack_h2(acc_o[nb][2 * r] * inv, acc_o[nb][2 * r + 1] * inv);
        }
    }
}

// ---------------------------------------------------------------------------
// Merge heads + residual + LayerNorm. One block (256 threads) per (b,t) row,
// 4 consecutive columns per thread (vectorized, fp16 ctx).
// ---------------------------------------------------------------------------
__global__ __launch_bounds__(256) void merge_ln_kernel(
    const float* __restrict__ qin,
    const float* __restrict__ gamma, const float* __restrict__ beta,
    float* __restrict__ out, int B, int T, int D, int depth)
{
    const int row = blockIdx.x;
    const int b = row / T, t = row % T;
    const int tid = threadIdx.x;
    const int cidx = tid * 4;

    const int head = cidx / depth, dd = cidx % depth;
    const __half2* cp = (const __half2*)(g_Ctx16 +
        (((size_t)head * B + b) * T + t) * depth + dd);
    half2 h0 = cp[0], h1 = cp[1];
    float4 qv = *(const float4*)(qin + (size_t)row * D + cidx);

    float vals[4];
    vals[0] = __low2float(h0)  + qv.x;
    vals[1] = __high2float(h0) + qv.y;
    vals[2] = __low2float(h1)  + qv.z;
    vals[3] = __high2float(h1) + qv.w;

    float sum = vals[0] + vals[1] + vals[2] + vals[3];
    float sq  = vals[0]*vals[0] + vals[1]*vals[1] + vals[2]*vals[2] + vals[3]*vals[3];
#pragma unroll
    for (int o = 16; o; o >>= 1) {
        sum += __shfl_xor_sync(0xffffffffu, sum, o);
        sq  += __shfl_xor_sync(0xffffffffu, sq, o);
    }
    __shared__ float s1[8], s2[8];
    int w = tid >> 5, l = tid & 31;
    if (l == 0) { s1[w] = sum; s2[w] = sq; }
    __syncthreads();
    if (w == 0) {
        sum = (l < 8) ? s1[l] : 0.f;
        sq  = (l < 8) ? s2[l] : 0.f;
#pragma unroll
        for (int o = 4; o; o >>= 1) {
            sum += __shfl_xor_sync(0xffffffffu, sum, o);
            sq  += __shfl_xor_sync(0xffffffffu, sq, o);
        }
        if (l == 0) { s1[0] = sum; s2[0] = sq; }
    }
    __syncthreads();
    sum = s1[0];
    sq  = s2[0];
    float mu  = sum / (float)D;
    float var = sq / (float)D - mu * mu;
    float inv = rsqrtf(var + 1e-5f);

    float4 g4 = *(const float4*)(gamma + cidx);
    float4 b4 = *(const float4*)(beta + cidx);
    float4 o4;
    o4.x = (vals[0] - mu) * inv * g4.x + b4.x;
    o4.y = (vals[1] - mu) * inv * g4.y + b4.y;
    o4.z = (vals[2] - mu) * inv * g4.z + b4.z;
    o4.w = (vals[3] - mu) * inv * g4.w + b4.w;
    *(float4*)(out + (size_t)row * D + cidx) = o4;
}

// ---------------------------------------------------------------------------
extern "C" void kernel_launch(void* const* d_in, const int* in_sizes, int n_in,
                              void* d_out, int out_size)
{
    const float* q    = (const float*)d_in[0];
    const float* k    = (const float*)d_in[1];
    const float* v    = (const float*)d_in[2];
    const int*   mask = (const int*)d_in[3];
    const int*   caus = (const int*)d_in[4];
    // d_in[5] = edge_fea (unused)
    const float* wq = (const float*)d_in[6];
    const float* bq = (const float*)d_in[7];
    const float* wk = (const float*)d_in[8];
    const float* bk = (const float*)d_in[9];
    const float* wv = (const float*)d_in[10];
    const float* bv = (const float*)d_in[11];
    const float* gamma = (const float*)d_in[12];
    const float* beta  = (const float*)d_in[13];
    float* out = (float*)d_out;

    const int D  = in_sizes[7];      // bq length
    const int BT = in_sizes[3];      // mask length = B*T
    int T = 2048;
    if (BT % T != 0) T = BT;
    const int B = BT / T;
    const int depth = D / NUM_HEADS;
    const int nA = BT * D;
    const int nW = D * D;

    cudaFuncSetAttribute(gemm_f16_kernel, cudaFuncAttributeMaxDynamicSharedMemorySize,
                         GEMM_SMEM_BYTES);
    cudaFuncSetAttribute(attn_f16_kernel, cudaFuncAttributeMaxDynamicSharedMemorySize,
                         ATTN_SMEM_BYTES);

    long totalCvt = 3L * nA + 3L * nW;
    int cvtBlocks = (int)((totalCvt / 8 + 255) / 256);
    cvt_all_kernel<<<cvtBlocks, 256>>>(q, k, v, wq, wk, wv, nA, nW);

    dim3 gemm_grid(D / 128, BT / 128, 3);
    gemm_f16_kernel<<<gemm_grid, 256, GEMM_SMEM_BYTES>>>(bq, bk, bv, D, B, T, depth);

    dim3 attn_grid(T / 128, NUM_HEADS * B);
    attn_f16_kernel<<<attn_grid, 256, ATTN_SMEM_BYTES>>>(mask, caus, B, T);

    merge_ln_kernel<<<BT, 256>>>(q, gamma, beta, out, B, T, D, depth);
}